// round 4
// baseline (speedup 1.0000x reference)
#include <cuda_runtime.h>
#include <cuda_bf16.h>
#include <cstdint>

// Problem constants
#define NN   50000
#define EE   800000
#define INC  128
#define HIDC 256
#define OUTC 128

// ---------------- device scratch (static globals; no allocation) ----------------
__device__ int   g_deg[NN];
__device__ int   g_rowstart[NN + 1];
__device__ int   g_cursor[NN];
__device__ int   g_col[EE];
__device__ float g_mean1[(size_t)NN * INC];   // 25.6 MB
__device__ float g_h[(size_t)NN * HIDC];      // 51.2 MB
__device__ float g_mean2[(size_t)NN * HIDC];  // 51.2 MB
__device__ int   g_is64;

// ---------------- init: zero degree histogram + detect edge dtype ----------------
__global__ void init_kernel(const void* __restrict__ ei_raw) {
    int stride = gridDim.x * blockDim.x;
    for (int i = blockIdx.x * blockDim.x + threadIdx.x; i < NN; i += stride)
        g_deg[i] = 0;
    // dtype detection: int64 values < 2^31 => odd 32-bit words are all zero.
    if (blockIdx.x == 0 && threadIdx.x < 32) {
        const unsigned* w = (const unsigned*)ei_raw;
        unsigned acc = 0;
        for (int i = threadIdx.x; i < 128; i += 32) acc |= w[2 * i + 1];
        #pragma unroll
        for (int off = 16; off; off >>= 1) acc |= __shfl_xor_sync(0xFFFFFFFFu, acc, off);
        if (threadIdx.x == 0) g_is64 = (acc == 0) ? 1 : 0;
    }
}

__device__ __forceinline__ int load_edge(const void* ei_raw, long long idx, int is64) {
    if (is64) return (int)((const long long*)ei_raw)[idx];
    return ((const int*)ei_raw)[idx];
}

// ---------------- histogram of dst degrees ----------------
__global__ void hist_kernel(const void* __restrict__ ei_raw) {
    int is64 = g_is64;
    int i = blockIdx.x * blockDim.x + threadIdx.x;
    if (i >= EE) return;
    int dst = load_edge(ei_raw, (long long)EE + i, is64);
    atomicAdd(&g_deg[dst], 1);
}

// ---------------- single-block exclusive scan over degrees ----------------
__global__ void scan_kernel() {
    __shared__ int warp_sums[32];
    __shared__ int carry_sh;
    int tid = threadIdx.x, lane = tid & 31, wid = tid >> 5;
    if (tid == 0) carry_sh = 0;
    __syncthreads();
    for (int base = 0; base < NN; base += 1024) {
        int i = base + tid;
        int v = (i < NN) ? g_deg[i] : 0;
        int x = v;
        #pragma unroll
        for (int off = 1; off < 32; off <<= 1) {
            int t = __shfl_up_sync(0xFFFFFFFFu, x, off);
            if (lane >= off) x += t;
        }
        if (lane == 31) warp_sums[wid] = x;
        __syncthreads();
        if (wid == 0) {
            int s = warp_sums[lane];
            #pragma unroll
            for (int off = 1; off < 32; off <<= 1) {
                int t = __shfl_up_sync(0xFFFFFFFFu, s, off);
                if (lane >= off) s += t;
            }
            warp_sums[lane] = s;
        }
        __syncthreads();
        int block_prefix = (wid > 0) ? warp_sums[wid - 1] : 0;
        int incl = block_prefix + x;
        int carry = carry_sh;
        if (i < NN) {
            int excl = carry + incl - v;
            g_rowstart[i] = excl;
            g_cursor[i]   = excl;
        }
        __syncthreads();
        if (tid == 1023) carry_sh = carry + incl;
        __syncthreads();
    }
    if (tid == 0) g_rowstart[NN] = EE;
}

// ---------------- scatter edges into CSR ----------------
__global__ void fill_kernel(const void* __restrict__ ei_raw) {
    int is64 = g_is64;
    int i = blockIdx.x * blockDim.x + threadIdx.x;
    if (i >= EE) return;
    int src = load_edge(ei_raw, (long long)i, is64);
    int dst = load_edge(ei_raw, (long long)EE + i, is64);
    int p = atomicAdd(&g_cursor[dst], 1);
    g_col[p] = src;
}

// ---------------- mean aggregation: one warp per node, edge-unrolled x2 ----------
// SRC==0: in = xin (param), out = g_mean1, C=INC
// SRC==1: in = g_h,         out = g_mean2, C=HIDC
template <int C, int SRC>
__global__ void agg_kernel(const float* __restrict__ xin) {
    const float* __restrict__ in  = (SRC == 0) ? xin : (const float*)g_h;
    float* __restrict__ out       = (SRC == 0) ? g_mean1 : g_mean2;

    int warp = (blockIdx.x * blockDim.x + threadIdx.x) >> 5;
    if (warp >= NN) return;
    int lane = threadIdx.x & 31;

    int beg = g_rowstart[warp];
    int end = g_rowstart[warp + 1];
    float inv = 1.0f / (float)max(end - beg, 1);

    constexpr int NV = C / 128;  // float4s per lane
    float4 acc0[NV], acc1[NV];
    #pragma unroll
    for (int v = 0; v < NV; v++) {
        acc0[v] = make_float4(0.f, 0.f, 0.f, 0.f);
        acc1[v] = make_float4(0.f, 0.f, 0.f, 0.f);
    }

    int j = beg;
    // unroll-2: two independent gather chains in flight
    for (; j + 1 < end; j += 2) {
        int s0 = g_col[j];
        int s1 = g_col[j + 1];
        const float4* r0 = (const float4*)(in + (size_t)s0 * C);
        const float4* r1 = (const float4*)(in + (size_t)s1 * C);
        float4 t0[NV], t1[NV];
        #pragma unroll
        for (int v = 0; v < NV; v++) t0[v] = __ldg(&r0[lane + v * 32]);
        #pragma unroll
        for (int v = 0; v < NV; v++) t1[v] = __ldg(&r1[lane + v * 32]);
        #pragma unroll
        for (int v = 0; v < NV; v++) {
            acc0[v].x += t0[v].x; acc0[v].y += t0[v].y;
            acc0[v].z += t0[v].z; acc0[v].w += t0[v].w;
            acc1[v].x += t1[v].x; acc1[v].y += t1[v].y;
            acc1[v].z += t1[v].z; acc1[v].w += t1[v].w;
        }
    }
    if (j < end) {
        int s = g_col[j];
        const float4* row = (const float4*)(in + (size_t)s * C);
        #pragma unroll
        for (int v = 0; v < NV; v++) {
            float4 t = __ldg(&row[lane + v * 32]);
            acc0[v].x += t.x; acc0[v].y += t.y;
            acc0[v].z += t.z; acc0[v].w += t.w;
        }
    }

    float4* orow = (float4*)(out + (size_t)warp * C);
    #pragma unroll
    for (int v = 0; v < NV; v++) {
        float4 r = make_float4((acc0[v].x + acc1[v].x) * inv,
                               (acc0[v].y + acc1[v].y) * inv,
                               (acc0[v].z + acc1[v].z) * inv,
                               (acc0[v].w + acc1[v].w) * inv);
        orow[lane + v * 32] = r;
    }
}

// ---------------- fused dual GEMM: out = A0 @ W0^T + A1 @ W1^T + bias (opt ReLU) --
// A*: [n_rows, K] row-major.  W*: [CO, K] row-major.  out: [n_rows, CO].
// LAYER==1: A0=g_mean1, A1=xin, out=g_h
// LAYER==2: A0=g_mean2, A1=g_h, out=outp
template <int K, int CO, bool RELU, int LAYER>
__global__ void __launch_bounds__(256)
gemm_dual(const float* __restrict__ xin,
          const float* __restrict__ W0, const float* __restrict__ W1,
          const float* __restrict__ bias, float* __restrict__ outp) {
    constexpr int BM = 128, BN = 128, BK = 16;
    constexpr int LDS_P = BM + 4;  // padded row

    const float* __restrict__ A0 = (LAYER == 1) ? (const float*)g_mean1 : (const float*)g_mean2;
    const float* __restrict__ A1 = (LAYER == 1) ? xin : (const float*)g_h;
    float* __restrict__ out      = (LAYER == 1) ? (float*)g_h : outp;

    __shared__ float As[BK][LDS_P];
    __shared__ float Bs[BK][LDS_P];

    int tid = threadIdx.x;
    int row0 = blockIdx.x * BM;
    int col0 = blockIdx.y * BN;
    int tx = tid & 15;         // 0..15 -> 8 output cols each
    int ty = tid >> 4;         // 0..15 -> 8 output rows each
    int lr = tid >> 2;         // 0..63 loader row
    int lk = (tid & 3) * 4;    // 0,4,8,12 loader k-offset

    float acc[8][8];
    #pragma unroll
    for (int i = 0; i < 8; i++)
        #pragma unroll
        for (int j = 0; j < 8; j++) acc[i][j] = 0.f;

    #pragma unroll
    for (int pass = 0; pass < 2; pass++) {
        const float* A = pass ? A1 : A0;
        const float* W = pass ? W1 : W0;
        for (int kk = 0; kk < K; kk += BK) {
            // load A tile (BM x BK) -> As[k][m]
            #pragma unroll
            for (int h = 0; h < 2; h++) {
                int r = row0 + lr + h * 64;
                int rc = min(r, NN - 1);
                float4 a = *(const float4*)(A + (size_t)rc * K + kk + lk);
                int m = lr + h * 64;
                As[lk + 0][m] = a.x; As[lk + 1][m] = a.y;
                As[lk + 2][m] = a.z; As[lk + 3][m] = a.w;
            }
            // load W tile (BN x BK) -> Bs[k][n]
            #pragma unroll
            for (int h = 0; h < 2; h++) {
                int r = col0 + lr + h * 64;  // always < CO
                float4 b = *(const float4*)(W + (size_t)r * K + kk + lk);
                int m = lr + h * 64;
                Bs[lk + 0][m] = b.x; Bs[lk + 1][m] = b.y;
                Bs[lk + 2][m] = b.z; Bs[lk + 3][m] = b.w;
            }
            __syncthreads();
            #pragma unroll
            for (int k = 0; k < BK; k++) {
                float a[8], b[8];
                *(float4*)(a + 0) = *(const float4*)&As[k][ty * 8 + 0];
                *(float4*)(a + 4) = *(const float4*)&As[k][ty * 8 + 4];
                *(float4*)(b + 0) = *(const float4*)&Bs[k][tx * 8 + 0];
                *(float4*)(b + 4) = *(const float4*)&Bs[k][tx * 8 + 4];
                #pragma unroll
                for (int i = 0; i < 8; i++)
                    #pragma unroll
                    for (int j = 0; j < 8; j++)
                        acc[i][j] += a[i] * b[j];
            }
            __syncthreads();
        }
    }

    // epilogue: bias (+ relu) + store
    #pragma unroll
    for (int i = 0; i < 8; i++) {
        int r = row0 + ty * 8 + i;
        if (r >= NN) continue;
        #pragma unroll
        for (int j = 0; j < 8; j += 4) {
            int c = col0 + tx * 8 + j;
            float4 v;
            v.x = acc[i][j + 0] + __ldg(&bias[c + 0]);
            v.y = acc[i][j + 1] + __ldg(&bias[c + 1]);
            v.z = acc[i][j + 2] + __ldg(&bias[c + 2]);
            v.w = acc[i][j + 3] + __ldg(&bias[c + 3]);
            if (RELU) {
                v.x = fmaxf(v.x, 0.f); v.y = fmaxf(v.y, 0.f);
                v.z = fmaxf(v.z, 0.f); v.w = fmaxf(v.w, 0.f);
            }
            *(float4*)(out + (size_t)r * CO + c) = v;
        }
    }
}

// ---------------- launch ----------------
extern "C" void kernel_launch(void* const* d_in, const int* in_sizes, int n_in,
                              void* d_out, int out_size) {
    const float* x   = (const float*)d_in[0];
    const void*  ei  = d_in[1];
    const float* W1l = (const float*)d_in[2];
    const float* b1  = (const float*)d_in[3];
    const float* W1r = (const float*)d_in[4];
    const float* W2l = (const float*)d_in[5];
    const float* b2  = (const float*)d_in[6];
    const float* W2r = (const float*)d_in[7];
    float* out = (float*)d_out;

    // CSR build
    init_kernel<<<196, 256>>>(ei);
    hist_kernel<<<(EE + 255) / 256, 256>>>(ei);
    scan_kernel<<<1, 1024>>>();
    fill_kernel<<<(EE + 255) / 256, 256>>>(ei);

    // layer 1
    agg_kernel<INC, 0><<<(NN + 7) / 8, 256>>>(x);
    {
        dim3 grid((NN + 127) / 128, HIDC / 128);
        gemm_dual<INC, HIDC, true, 1><<<grid, 256>>>(x, W1l, W1r, b1, nullptr);
    }
    // layer 2
    agg_kernel<HIDC, 1><<<(NN + 7) / 8, 256>>>(nullptr);
    {
        dim3 grid((NN + 127) / 128, OUTC / 128);
        gemm_dual<HIDC, OUTC, false, 2><<<grid, 256>>>(nullptr, W2l, W2r, b2, out);
    }
}

// round 7
// speedup vs baseline: 1.0651x; 1.0651x over previous
#include <cuda_runtime.h>
#include <cuda_bf16.h>
#include <cstdint>

// Problem constants
#define NN   50000
#define EE   800000
#define INC  128
#define HIDC 256
#define OUTC 128

// ---------------- device scratch (static globals; no allocation) ----------------
__device__ int   g_deg[NN];
__device__ int   g_rowstart[NN + 1];
__device__ int   g_cursor[NN];
__device__ int   g_col[EE];
__device__ float g_mean1[(size_t)NN * INC];   // layer1 mean; reused as p = h@W2l^T
__device__ float g_h[(size_t)NN * HIDC];      // hidden activations
__device__ float g_q[(size_t)NN * OUTC];      // q = h@W2r^T + b2
__device__ int   g_is64;

// ---------------- init: zero degree histogram + detect edge dtype ----------------
__global__ void init_kernel(const void* __restrict__ ei_raw) {
    int stride = gridDim.x * blockDim.x;
    for (int i = blockIdx.x * blockDim.x + threadIdx.x; i < NN; i += stride)
        g_deg[i] = 0;
    // dtype detection: int64 values < 2^31 => odd 32-bit words are all zero.
    if (blockIdx.x == 0 && threadIdx.x < 32) {
        const unsigned* w = (const unsigned*)ei_raw;
        unsigned acc = 0;
        for (int i = threadIdx.x; i < 128; i += 32) acc |= w[2 * i + 1];
        #pragma unroll
        for (int off = 16; off; off >>= 1) acc |= __shfl_xor_sync(0xFFFFFFFFu, acc, off);
        if (threadIdx.x == 0) g_is64 = (acc == 0) ? 1 : 0;
    }
}

__device__ __forceinline__ int load_edge(const void* ei_raw, long long idx, int is64) {
    if (is64) return (int)((const long long*)ei_raw)[idx];
    return ((const int*)ei_raw)[idx];
}

// ---------------- histogram of dst degrees ----------------
__global__ void hist_kernel(const void* __restrict__ ei_raw) {
    int is64 = g_is64;
    int i = blockIdx.x * blockDim.x + threadIdx.x;
    if (i >= EE) return;
    int dst = load_edge(ei_raw, (long long)EE + i, is64);
    atomicAdd(&g_deg[dst], 1);
}

// ---------------- single-block exclusive scan over degrees ----------------
__global__ void scan_kernel() {
    __shared__ int warp_sums[32];
    __shared__ int carry_sh;
    int tid = threadIdx.x, lane = tid & 31, wid = tid >> 5;
    if (tid == 0) carry_sh = 0;
    __syncthreads();
    for (int base = 0; base < NN; base += 1024) {
        int i = base + tid;
        int v = (i < NN) ? g_deg[i] : 0;
        int x = v;
        #pragma unroll
        for (int off = 1; off < 32; off <<= 1) {
            int t = __shfl_up_sync(0xFFFFFFFFu, x, off);
            if (lane >= off) x += t;
        }
        if (lane == 31) warp_sums[wid] = x;
        __syncthreads();
        if (wid == 0) {
            int s = warp_sums[lane];
            #pragma unroll
            for (int off = 1; off < 32; off <<= 1) {
                int t = __shfl_up_sync(0xFFFFFFFFu, s, off);
                if (lane >= off) s += t;
            }
            warp_sums[lane] = s;
        }
        __syncthreads();
        int block_prefix = (wid > 0) ? warp_sums[wid - 1] : 0;
        int incl = block_prefix + x;
        int carry = carry_sh;
        if (i < NN) {
            int excl = carry + incl - v;
            g_rowstart[i] = excl;
            g_cursor[i]   = excl;
        }
        __syncthreads();
        if (tid == 1023) carry_sh = carry + incl;
        __syncthreads();
    }
    if (tid == 0) g_rowstart[NN] = EE;
}

// ---------------- scatter edges into CSR ----------------
__global__ void fill_kernel(const void* __restrict__ ei_raw) {
    int is64 = g_is64;
    int i = blockIdx.x * blockDim.x + threadIdx.x;
    if (i >= EE) return;
    int src = load_edge(ei_raw, (long long)i, is64);
    int dst = load_edge(ei_raw, (long long)EE + i, is64);
    int p = atomicAdd(&g_cursor[dst], 1);
    g_col[p] = src;
}

// ---------------- mean aggregation over 128-channel features -------------------
// MODE 0: out = mean_agg(xin)                    (layer-1: x -> g_mean1)
// MODE 1: out = mean_agg(g_mean1 (=p)) + g_q     (layer-2 final: -> d_out)
template <int MODE>
__global__ void agg128_kernel(const float* __restrict__ xin, float* __restrict__ outp) {
    const float* __restrict__ in = (MODE == 0) ? xin : (const float*)g_mean1;
    float* __restrict__ out      = (MODE == 0) ? (float*)g_mean1 : outp;

    int warp = (blockIdx.x * blockDim.x + threadIdx.x) >> 5;
    if (warp >= NN) return;
    int lane = threadIdx.x & 31;

    int beg = g_rowstart[warp];
    int end = g_rowstart[warp + 1];
    float inv = 1.0f / (float)max(end - beg, 1);

    float4 acc0 = make_float4(0.f, 0.f, 0.f, 0.f);
    float4 acc1 = make_float4(0.f, 0.f, 0.f, 0.f);

    int j = beg;
    for (; j + 1 < end; j += 2) {
        int s0 = g_col[j];
        int s1 = g_col[j + 1];
        float4 t0 = __ldg((const float4*)(in + (size_t)s0 * 128) + lane);
        float4 t1 = __ldg((const float4*)(in + (size_t)s1 * 128) + lane);
        acc0.x += t0.x; acc0.y += t0.y; acc0.z += t0.z; acc0.w += t0.w;
        acc1.x += t1.x; acc1.y += t1.y; acc1.z += t1.z; acc1.w += t1.w;
    }
    if (j < end) {
        int s = g_col[j];
        float4 t = __ldg((const float4*)(in + (size_t)s * 128) + lane);
        acc0.x += t.x; acc0.y += t.y; acc0.z += t.z; acc0.w += t.w;
    }

    float4 r = make_float4((acc0.x + acc1.x) * inv, (acc0.y + acc1.y) * inv,
                           (acc0.z + acc1.z) * inv, (acc0.w + acc1.w) * inv);
    if (MODE == 1) {
        float4 qv = __ldg((const float4*)((const float*)g_q + (size_t)warp * 128) + lane);
        r.x += qv.x; r.y += qv.y; r.z += qv.z; r.w += qv.w;
    }
    ((float4*)(out + (size_t)warp * 128))[lane] = r;
}

// ---------------- tf32 tensor-core GEMM (3xTF32 error-compensated) -------------
__device__ __forceinline__ unsigned f2tf32(float x) {
    unsigned r;
    asm("cvt.rna.tf32.f32 %0, %1;" : "=r"(r) : "f"(x));
    return r;
}

__device__ __forceinline__ void mma_tf32(float c[4], const unsigned a[4], const unsigned b[2]) {
    asm volatile(
        "mma.sync.aligned.m16n8k8.row.col.f32.tf32.tf32.f32 "
        "{%0,%1,%2,%3},{%4,%5,%6,%7},{%8,%9},{%0,%1,%2,%3};"
        : "+f"(c[0]), "+f"(c[1]), "+f"(c[2]), "+f"(c[3])
        : "r"(a[0]), "r"(a[1]), "r"(a[2]), "r"(a[3]), "r"(b[0]), "r"(b[1]));
}

#define G_BK 16
#define G_LD 136   // 128 + 8 pad -> conflict-free fragment loads (136 mod 32 == 8)

__device__ __forceinline__ void load_split_tile(
    const float* __restrict__ G, int row0, int rowmax, int stride, int kk,
    unsigned (*Sh)[G_LD], unsigned (*Sl)[G_LD], int t) {
    #pragma unroll
    for (int u = 0; u < 2; u++) {
        int idx = t + u * 256;
        int row = idx >> 2;
        int kq  = (idx & 3) << 2;
        int r = min(row0 + row, rowmax);
        float4 v = *(const float4*)(G + (size_t)r * stride + kk + kq);
        float f[4] = {v.x, v.y, v.z, v.w};
        #pragma unroll
        for (int jj = 0; jj < 4; jj++) {
            unsigned hb = f2tf32(f[jj]);
            float lo = f[jj] - __uint_as_float(hb);
            Sh[kq + jj][row] = hb;
            Sl[kq + jj][row] = f2tf32(lo);
        }
    }
}

// MODE 0 (layer 1): out[M,256] = g_mean1@W0^T + xin@W1^T + bias, ReLU -> g_h
//                   grid (391, 2); blockIdx.y selects the 128-col half.
// MODE 1 (layer 2): grid (391, 2);
//                   y==0: g_mean1(p) = g_h@W0^T           (no bias)
//                   y==1: g_q        = g_h@W1^T + bias
template <int K, int MODE>
__global__ void __launch_bounds__(256)
gemm_tf32(const float* __restrict__ xin,
          const float* __restrict__ W0p, const float* __restrict__ W1p,
          const float* __restrict__ biasp, float* __restrict__ unused) {
    __shared__ unsigned As_hi[G_BK][G_LD], As_lo[G_BK][G_LD];
    __shared__ unsigned Bs_hi[G_BK][G_LD], Bs_lo[G_BK][G_LD];

    const int t    = threadIdx.x;
    const int wid  = t >> 5;
    const int lane = t & 31;
    const int g    = lane >> 2;   // group id 0..7
    const int tig  = lane & 3;    // thread-in-group 0..3
    const int wm   = wid & 3;     // warp m index (0..3), 32 rows each
    const int wn   = wid >> 2;    // warp n index (0..1), 64 cols each
    const int row0 = blockIdx.x * 128;
    const int by   = blockIdx.y;

    float*       out;
    const float* bias;
    int          ldout, outcol0, wrow0;
    if (MODE == 0) {
        out = (float*)g_h; bias = biasp; ldout = HIDC; outcol0 = by * 128; wrow0 = by * 128;
    } else {
        out = (by == 0) ? (float*)g_mean1 : (float*)g_q;
        bias = (by == 0) ? nullptr : biasp;
        ldout = 128; outcol0 = 0; wrow0 = 0;
    }

    float acc[2][8][4];
    #pragma unroll
    for (int im = 0; im < 2; im++)
        #pragma unroll
        for (int in_ = 0; in_ < 8; in_++)
            #pragma unroll
            for (int c = 0; c < 4; c++) acc[im][in_][c] = 0.f;

    const int npass = (MODE == 0) ? 2 : 1;
    #pragma unroll
    for (int pass = 0; pass < npass; pass++) {
        const float* A;
        const float* W;
        if (MODE == 0) {
            A = pass ? xin : (const float*)g_mean1;
            W = pass ? W1p : W0p;
        } else {
            A = (const float*)g_h;
            W = (by == 0) ? W0p : W1p;
        }
        for (int kk = 0; kk < K; kk += G_BK) {
            load_split_tile(A, row0, NN - 1, K, kk, As_hi, As_lo, t);
            load_split_tile(W, wrow0, 1 << 28, K, kk, Bs_hi, Bs_lo, t);
            __syncthreads();
            #pragma unroll
            for (int k8 = 0; k8 < G_BK; k8 += 8) {
                const int ks = k8 + tig;
                unsigned ah[2][4], al[2][4], bh[8][2], bl[8][2];
                #pragma unroll
                for (int im = 0; im < 2; im++) {
                    int m = wm * 32 + im * 16 + g;
                    ah[im][0] = As_hi[ks][m];     ah[im][1] = As_hi[ks][m + 8];
                    ah[im][2] = As_hi[ks + 4][m]; ah[im][3] = As_hi[ks + 4][m + 8];
                    al[im][0] = As_lo[ks][m];     al[im][1] = As_lo[ks][m + 8];
                    al[im][2] = As_lo[ks + 4][m]; al[im][3] = As_lo[ks + 4][m + 8];
                }
                #pragma unroll
                for (int in_ = 0; in_ < 8; in_++) {
                    int n = wn * 64 + in_ * 8 + g;
                    bh[in_][0] = Bs_hi[ks][n]; bh[in_][1] = Bs_hi[ks + 4][n];
                    bl[in_][0] = Bs_lo[ks][n]; bl[in_][1] = Bs_lo[ks + 4][n];
                }
                #pragma unroll
                for (int im = 0; im < 2; im++)
                    #pragma unroll
                    for (int in_ = 0; in_ < 8; in_++) {
                        mma_tf32(acc[im][in_], ah[im], bl[in_]);  // hi*lo
                        mma_tf32(acc[im][in_], al[im], bh[in_]);  // lo*hi
                        mma_tf32(acc[im][in_], ah[im], bh[in_]);  // hi*hi
                    }
            }
            __syncthreads();
        }
    }

    // epilogue
    #pragma unroll
    for (int im = 0; im < 2; im++) {
        #pragma unroll
        for (int in_ = 0; in_ < 8; in_++) {
            int col = outcol0 + wn * 64 + in_ * 8 + 2 * tig;
            float bx = 0.f, byv = 0.f;
            if (bias) { bx = __ldg(bias + col); byv = __ldg(bias + col + 1); }
            int r0 = row0 + wm * 32 + im * 16 + g;
            #pragma unroll
            for (int half = 0; half < 2; half++) {
                int r = r0 + half * 8;
                if (r < NN) {
                    float vx = acc[im][in_][2 * half + 0] + bx;
                    float vy = acc[im][in_][2 * half + 1] + byv;
                    if (MODE == 0) { vx = fmaxf(vx, 0.f); vy = fmaxf(vy, 0.f); }
                    *(float2*)(out + (size_t)r * ldout + col) = make_float2(vx, vy);
                }
            }
        }
    }
}

// ---------------- launch ----------------
extern "C" void kernel_launch(void* const* d_in, const int* in_sizes, int n_in,
                              void* d_out, int out_size) {
    const float* x   = (const float*)d_in[0];
    const void*  ei  = d_in[1];
    const float* W1l = (const float*)d_in[2];
    const float* b1  = (const float*)d_in[3];
    const float* W1r = (const float*)d_in[4];
    const float* W2l = (const float*)d_in[5];
    const float* b2  = (const float*)d_in[6];
    const float* W2r = (const float*)d_in[7];
    float* out = (float*)d_out;

    // CSR build
    init_kernel<<<196, 256>>>(ei);
    hist_kernel<<<(EE + 255) / 256, 256>>>(ei);
    scan_kernel<<<1, 1024>>>();
    fill_kernel<<<(EE + 255) / 256, 256>>>(ei);

    // layer 1: mean1 = agg(x);  h = relu(mean1@W1l^T + x@W1r^T + b1)
    agg128_kernel<0><<<(NN + 7) / 8, 256>>>(x, nullptr);
    gemm_tf32<INC, 0><<<dim3((NN + 127) / 128, 2), 256>>>(x, W1l, W1r, b1, nullptr);

    // layer 2: p = h@W2l^T; q = h@W2r^T + b2;  out = agg(p) + q
    gemm_tf32<HIDC, 1><<<dim3((NN + 127) / 128, 2), 256>>>(nullptr, W2l, W2r, b2, nullptr);
    agg128_kernel<1><<<(NN + 7) / 8, 256>>>(nullptr, out);
}

// round 11
// speedup vs baseline: 1.9910x; 1.8692x over previous
#include <cuda_runtime.h>
#include <cuda_bf16.h>
#include <cstdint>

// Problem constants
#define NN   50000
#define EE   800000
#define INC  128
#define HIDC 256
#define OUTC 128

// ---------------- device scratch (static globals; no allocation) ----------------
__device__ int   g_deg[NN];
__device__ int   g_rowstart[NN + 1];
__device__ int   g_cursor[NN];
__device__ int   g_col[EE];
__device__ int   g_is64;

// bf16 limb planes (hi/lo) for GEMM operands
__device__ unsigned short g_xh [(size_t)NN * INC],  g_xl [(size_t)NN * INC];
__device__ unsigned short g_m1h[(size_t)NN * INC],  g_m1l[(size_t)NN * INC];
__device__ unsigned short g_hh [(size_t)NN * HIDC], g_hl [(size_t)NN * HIDC];
__device__ float g_p[(size_t)NN * OUTC];   // p = h @ W2l^T
__device__ float g_q[(size_t)NN * OUTC];   // q = h @ W2r^T + b2

// weight limb planes
__device__ unsigned short g_w1lh[HIDC * INC],  g_w1ll[HIDC * INC];
__device__ unsigned short g_w1rh[HIDC * INC],  g_w1rl[HIDC * INC];
__device__ unsigned short g_w2lh[OUTC * HIDC], g_w2ll[OUTC * HIDC];
__device__ unsigned short g_w2rh[OUTC * HIDC], g_w2rl[OUTC * HIDC];

__device__ __forceinline__ void split1(float v, unsigned short& h, unsigned short& l) {
    __nv_bfloat16 hb = __float2bfloat16_rn(v);
    float lo = v - __bfloat162float(hb);
    __nv_bfloat16 lb = __float2bfloat16_rn(lo);
    h = *(unsigned short*)&hb;
    l = *(unsigned short*)&lb;
}

// ---------------- init: zero degree histogram + detect edge dtype ----------------
__global__ void init_kernel(const void* __restrict__ ei_raw) {
    int stride = gridDim.x * blockDim.x;
    for (int i = blockIdx.x * blockDim.x + threadIdx.x; i < NN; i += stride)
        g_deg[i] = 0;
    if (blockIdx.x == 0 && threadIdx.x < 32) {
        const unsigned* w = (const unsigned*)ei_raw;
        unsigned acc = 0;
        for (int i = threadIdx.x; i < 128; i += 32) acc |= w[2 * i + 1];
        #pragma unroll
        for (int off = 16; off; off >>= 1) acc |= __shfl_xor_sync(0xFFFFFFFFu, acc, off);
        if (threadIdx.x == 0) g_is64 = (acc == 0) ? 1 : 0;
    }
}

__device__ __forceinline__ int load_edge(const void* ei_raw, long long idx, int is64) {
    if (is64) return (int)((const long long*)ei_raw)[idx];
    return ((const int*)ei_raw)[idx];
}

__global__ void hist_kernel(const void* __restrict__ ei_raw) {
    int is64 = g_is64;
    int i = blockIdx.x * blockDim.x + threadIdx.x;
    if (i >= EE) return;
    int dst = load_edge(ei_raw, (long long)EE + i, is64);
    atomicAdd(&g_deg[dst], 1);
}

__global__ void scan_kernel() {
    __shared__ int warp_sums[32];
    __shared__ int carry_sh;
    int tid = threadIdx.x, lane = tid & 31, wid = tid >> 5;
    if (tid == 0) carry_sh = 0;
    __syncthreads();
    for (int base = 0; base < NN; base += 1024) {
        int i = base + tid;
        int v = (i < NN) ? g_deg[i] : 0;
        int x = v;
        #pragma unroll
        for (int off = 1; off < 32; off <<= 1) {
            int t = __shfl_up_sync(0xFFFFFFFFu, x, off);
            if (lane >= off) x += t;
        }
        if (lane == 31) warp_sums[wid] = x;
        __syncthreads();
        if (wid == 0) {
            int s = warp_sums[lane];
            #pragma unroll
            for (int off = 1; off < 32; off <<= 1) {
                int t = __shfl_up_sync(0xFFFFFFFFu, s, off);
                if (lane >= off) s += t;
            }
            warp_sums[lane] = s;
        }
        __syncthreads();
        int block_prefix = (wid > 0) ? warp_sums[wid - 1] : 0;
        int incl = block_prefix + x;
        int carry = carry_sh;
        if (i < NN) {
            int excl = carry + incl - v;
            g_rowstart[i] = excl;
            g_cursor[i]   = excl;
        }
        __syncthreads();
        if (tid == 1023) carry_sh = carry + incl;
        __syncthreads();
    }
    if (tid == 0) g_rowstart[NN] = EE;
}

__global__ void fill_kernel(const void* __restrict__ ei_raw) {
    int is64 = g_is64;
    int i = blockIdx.x * blockDim.x + threadIdx.x;
    if (i >= EE) return;
    int src = load_edge(ei_raw, (long long)i, is64);
    int dst = load_edge(ei_raw, (long long)EE + i, is64);
    int p = atomicAdd(&g_cursor[dst], 1);
    g_col[p] = src;
}

// ---------------- weight / x splitting ----------------
__global__ void split_w_kernel(const float* __restrict__ W1l, const float* __restrict__ W1r,
                               const float* __restrict__ W2l, const float* __restrict__ W2r) {
    const int S = HIDC * INC;  // 32768, same size for all four
    int i = blockIdx.x * blockDim.x + threadIdx.x;
    if (i < S)              split1(W1l[i], g_w1lh[i], g_w1ll[i]);
    else if (i < 2 * S)   { int j = i - S;     split1(W1r[j], g_w1rh[j], g_w1rl[j]); }
    else if (i < 3 * S)   { int j = i - 2 * S; split1(W2l[j], g_w2lh[j], g_w2ll[j]); }
    else if (i < 4 * S)   { int j = i - 3 * S; split1(W2r[j], g_w2rh[j], g_w2rl[j]); }
}

__global__ void split_x_kernel(const float* __restrict__ x) {
    int i = blockIdx.x * blockDim.x + threadIdx.x;  // float4 index
    if (i >= NN * INC / 4) return;
    float4 v = ((const float4*)x)[i];
    ushort4 hv, lv;
    split1(v.x, hv.x, lv.x); split1(v.y, hv.y, lv.y);
    split1(v.z, hv.z, lv.z); split1(v.w, hv.w, lv.w);
    ((ushort4*)g_xh)[i] = hv;
    ((ushort4*)g_xl)[i] = lv;
}

// ---------------- mean aggregation over 128-channel features -------------------
// MODE 0: m1 = mean_agg(x), written as bf16 hi/lo planes
// MODE 1: out = mean_agg(g_p) + g_q  (fp32, final output)
template <int MODE>
__global__ void agg128_kernel(const float* __restrict__ xin, float* __restrict__ outp) {
    const float* __restrict__ in = (MODE == 0) ? xin : (const float*)g_p;

    int warp = (blockIdx.x * blockDim.x + threadIdx.x) >> 5;
    if (warp >= NN) return;
    int lane = threadIdx.x & 31;

    int beg = g_rowstart[warp];
    int end = g_rowstart[warp + 1];
    float inv = 1.0f / (float)max(end - beg, 1);

    float4 acc0 = make_float4(0.f, 0.f, 0.f, 0.f);
    float4 acc1 = make_float4(0.f, 0.f, 0.f, 0.f);

    int j = beg;
    for (; j + 1 < end; j += 2) {
        int s0 = g_col[j];
        int s1 = g_col[j + 1];
        float4 t0 = __ldg((const float4*)(in + (size_t)s0 * 128) + lane);
        float4 t1 = __ldg((const float4*)(in + (size_t)s1 * 128) + lane);
        acc0.x += t0.x; acc0.y += t0.y; acc0.z += t0.z; acc0.w += t0.w;
        acc1.x += t1.x; acc1.y += t1.y; acc1.z += t1.z; acc1.w += t1.w;
    }
    if (j < end) {
        int s = g_col[j];
        float4 t = __ldg((const float4*)(in + (size_t)s * 128) + lane);
        acc0.x += t.x; acc0.y += t.y; acc0.z += t.z; acc0.w += t.w;
    }

    float4 r = make_float4((acc0.x + acc1.x) * inv, (acc0.y + acc1.y) * inv,
                           (acc0.z + acc1.z) * inv, (acc0.w + acc1.w) * inv);
    if (MODE == 0) {
        ushort4 hv, lv;
        split1(r.x, hv.x, lv.x); split1(r.y, hv.y, lv.y);
        split1(r.z, hv.z, lv.z); split1(r.w, hv.w, lv.w);
        ((ushort4*)g_m1h)[(size_t)warp * 32 + lane] = hv;
        ((ushort4*)g_m1l)[(size_t)warp * 32 + lane] = lv;
    } else {
        float4 qv = __ldg((const float4*)((const float*)g_q + (size_t)warp * 128) + lane);
        r.x += qv.x; r.y += qv.y; r.z += qv.z; r.w += qv.w;
        ((float4*)(outp + (size_t)warp * 128))[lane] = r;
    }
}

// ---------------- bf16 2-limb tensor-core GEMM (3-product compensation) --------
__device__ __forceinline__ void mma_bf16(float c[4], const unsigned a[4], const unsigned b[2]) {
    asm volatile(
        "mma.sync.aligned.m16n8k16.row.col.f32.bf16.bf16.f32 "
        "{%0,%1,%2,%3},{%4,%5,%6,%7},{%8,%9},{%0,%1,%2,%3};"
        : "+f"(c[0]), "+f"(c[1]), "+f"(c[2]), "+f"(c[3])
        : "r"(a[0]), "r"(a[1]), "r"(a[2]), "r"(a[3]), "r"(b[0]), "r"(b[1]));
}

#define S_LD 36  // 32 + 4 halves pad: 72B row stride -> conflict-free frag loads

// MODE 0 (layer 1): grid (391,2). out cols [by*128, by*128+128) of h:
//    h = relu(m1 @ W1l^T + x @ W1r^T + b1), stored as bf16 hi/lo planes g_hh/g_hl.
// MODE 1 (layer 2): grid (391,2).
//    by==0: g_p = h @ W2l^T      by==1: g_q = h @ W2r^T + b2   (fp32 outputs)
template <int K, int MODE>
__global__ void __launch_bounds__(256)
gemm_bf16(const float* __restrict__ biasp, float* __restrict__ unused) {
    __shared__ unsigned short Ah[128][S_LD], Al[128][S_LD];
    __shared__ unsigned short Bh[128][S_LD], Bl[128][S_LD];

    const int t    = threadIdx.x;
    const int wid  = t >> 5;
    const int lane = t & 31;
    const int g    = lane >> 2;
    const int tig  = lane & 3;
    const int wm   = wid & 3;    // 4 warps over M: 32 rows each
    const int wn   = wid >> 2;   // 2 warps over N: 64 cols each
    const int row0 = blockIdx.x * 128;
    const int by   = blockIdx.y;

    float acc[2][8][4];
    #pragma unroll
    for (int im = 0; im < 2; im++)
        #pragma unroll
        for (int in_ = 0; in_ < 8; in_++)
            #pragma unroll
            for (int c = 0; c < 4; c++) acc[im][in_][c] = 0.f;

    const int npass = (MODE == 0) ? 2 : 1;
    #pragma unroll
    for (int pass = 0; pass < npass; pass++) {
        const unsigned short *Aph, *Apl, *Wph, *Wpl;
        int wrow0;
        if (MODE == 0) {
            Aph = pass ? g_xh : g_m1h;  Apl = pass ? g_xl : g_m1l;
            Wph = pass ? g_w1rh : g_w1lh;  Wpl = pass ? g_w1rl : g_w1ll;
            wrow0 = by * 128;
        } else {
            Aph = g_hh; Apl = g_hl;
            Wph = (by == 0) ? g_w2lh : g_w2rh;
            Wpl = (by == 0) ? g_w2ll : g_w2rl;
            wrow0 = 0;
        }

        for (int kk = 0; kk < K; kk += 32) {
            // load 128x32-half tiles (hi+lo planes) for A and W.
            // 128 rows x 8 uint2-per-row = 1024 items; 256 threads x u<4.
            #pragma unroll
            for (int u = 0; u < 4; u++) {
                int idx = t + u * 256;
                int row = idx >> 3;
                int c8  = (idx & 7) * 4;   // halves offset, 8B-aligned
                int r  = min(row0 + row, NN - 1);
                int wr = wrow0 + row;
                uint2 vah = *(const uint2*)(Aph + (size_t)r * K + kk + c8);
                uint2 val = *(const uint2*)(Apl + (size_t)r * K + kk + c8);
                uint2 vbh = *(const uint2*)(Wph + (size_t)wr * K + kk + c8);
                uint2 vbl = *(const uint2*)(Wpl + (size_t)wr * K + kk + c8);
                *(uint2*)&Ah[row][c8] = vah;
                *(uint2*)&Al[row][c8] = val;
                *(uint2*)&Bh[row][c8] = vbh;
                *(uint2*)&Bl[row][c8] = vbl;
            }
            __syncthreads();

            #pragma unroll
            for (int o = 0; o < 32; o += 16) {
                unsigned ah[2][4], al[2][4], bh[8][2], bl[8][2];
                #pragma unroll
                for (int im = 0; im < 2; im++) {
                    int m = wm * 32 + im * 16 + g;
                    int c0 = o + 2 * tig;
                    ah[im][0] = *(const unsigned*)&Ah[m][c0];
                    ah[im][1] = *(const unsigned*)&Ah[m + 8][c0];
                    ah[im][2] = *(const unsigned*)&Ah[m][c0 + 8];
                    ah[im][3] = *(const unsigned*)&Ah[m + 8][c0 + 8];
                    al[im][0] = *(const unsigned*)&Al[m][c0];
                    al[im][1] = *(const unsigned*)&Al[m + 8][c0];
                    al[im][2] = *(const unsigned*)&Al[m][c0 + 8];
                    al[im][3] = *(const unsigned*)&Al[m + 8][c0 + 8];
                }
                #pragma unroll
                for (int in_ = 0; in_ < 8; in_++) {
                    int n = wn * 64 + in_ * 8 + g;
                    int c0 = o + 2 * tig;
                    bh[in_][0] = *(const unsigned*)&Bh[n][c0];
                    bh[in_][1] = *(const unsigned*)&Bh[n][c0 + 8];
                    bl[in_][0] = *(const unsigned*)&Bl[n][c0];
                    bl[in_][1] = *(const unsigned*)&Bl[n][c0 + 8];
                }
                #pragma unroll
                for (int im = 0; im < 2; im++)
                    #pragma unroll
                    for (int in_ = 0; in_ < 8; in_++) {
                        mma_bf16(acc[im][in_], ah[im], bl[in_]);  // hi*lo
                        mma_bf16(acc[im][in_], al[im], bh[in_]);  // lo*hi
                        mma_bf16(acc[im][in_], ah[im], bh[in_]);  // hi*hi
                    }
            }
            __syncthreads();
        }
    }

    // epilogue
    const float* bias = (MODE == 0) ? biasp : ((by == 1) ? biasp : nullptr);
    const int outcol0 = (MODE == 0) ? by * 128 : 0;
    #pragma unroll
    for (int im = 0; im < 2; im++) {
        #pragma unroll
        for (int in_ = 0; in_ < 8; in_++) {
            int col  = wn * 64 + in_ * 8 + 2 * tig;
            int gcol = outcol0 + col;
            float bx = 0.f, byv = 0.f;
            if (bias) { bx = __ldg(bias + gcol); byv = __ldg(bias + gcol + 1); }
            int r0 = row0 + wm * 32 + im * 16 + g;
            #pragma unroll
            for (int half = 0; half < 2; half++) {
                int r = r0 + half * 8;
                if (r >= NN) continue;
                float vx = acc[im][in_][2 * half + 0] + bx;
                float vy = acc[im][in_][2 * half + 1] + byv;
                if (MODE == 0) {
                    vx = fmaxf(vx, 0.f); vy = fmaxf(vy, 0.f);
                    unsigned short hx, lx, hy, ly;
                    split1(vx, hx, lx); split1(vy, hy, ly);
                    *(unsigned*)&g_hh[(size_t)r * HIDC + gcol] = (unsigned)hx | ((unsigned)hy << 16);
                    *(unsigned*)&g_hl[(size_t)r * HIDC + gcol] = (unsigned)lx | ((unsigned)ly << 16);
                } else {
                    float* out = (by == 0) ? g_p : g_q;
                    *(float2*)(out + (size_t)r * OUTC + col) = make_float2(vx, vy);
                }
            }
        }
    }
}

// ---------------- launch ----------------
extern "C" void kernel_launch(void* const* d_in, const int* in_sizes, int n_in,
                              void* d_out, int out_size) {
    const float* x   = (const float*)d_in[0];
    const void*  ei  = d_in[1];
    const float* W1l = (const float*)d_in[2];
    const float* b1  = (const float*)d_in[3];
    const float* W1r = (const float*)d_in[4];
    const float* W2l = (const float*)d_in[5];
    const float* b2  = (const float*)d_in[6];
    const float* W2r = (const float*)d_in[7];
    float* out = (float*)d_out;

    // CSR build
    init_kernel<<<196, 256>>>(ei);
    hist_kernel<<<(EE + 255) / 256, 256>>>(ei);
    scan_kernel<<<1, 1024>>>();
    fill_kernel<<<(EE + 255) / 256, 256>>>(ei);

    // operand limb splits
    split_w_kernel<<<(4 * HIDC * INC + 255) / 256, 256>>>(W1l, W1r, W2l, W2r);
    split_x_kernel<<<(NN * INC / 4 + 255) / 256, 256>>>(x);

    // layer 1: m1 = agg(x);  h = relu(m1@W1l^T + x@W1r^T + b1)  (bf16 limb planes)
    agg128_kernel<0><<<(NN + 7) / 8, 256>>>(x, nullptr);
    gemm_bf16<INC, 0><<<dim3((NN + 127) / 128, 2), 256>>>(b1, nullptr);

    // layer 2: p = h@W2l^T; q = h@W2r^T + b2;  out = agg(p) + q
    gemm_bf16<HIDC, 1><<<dim3((NN + 127) / 128, 2), 256>>>(b2, nullptr);
    agg128_kernel<1><<<(NN + 7) / 8, 256>>>(nullptr, out);
}

// round 12
// speedup vs baseline: 2.3611x; 1.1859x over previous
#include <cuda_runtime.h>
#include <cuda_bf16.h>
#include <cstdint>

// Problem constants
#define NN   50000
#define EE   800000
#define INC  128
#define HIDC 256
#define OUTC 128

// ---------------- device scratch (static globals; no allocation) ----------------
__device__ int   g_deg[NN];
__device__ int   g_rowstart[NN + 1];
__device__ int   g_cursor[NN];
__device__ int   g_col[EE];
__device__ int   g_is64;
__device__ int   g_bsum[256];

// bf16 limb planes (hi/lo) for GEMM operands
__device__ unsigned short g_xh [(size_t)NN * INC],  g_xl [(size_t)NN * INC];
__device__ unsigned short g_m1h[(size_t)NN * INC],  g_m1l[(size_t)NN * INC];
__device__ unsigned short g_hh [(size_t)NN * HIDC], g_hl [(size_t)NN * HIDC];
__device__ float g_p[(size_t)NN * OUTC];   // p = h @ W2l^T
__device__ float g_q[(size_t)NN * OUTC];   // q = h @ W2r^T + b2

// weight limb planes
__device__ unsigned short g_w1lh[HIDC * INC],  g_w1ll[HIDC * INC];
__device__ unsigned short g_w1rh[HIDC * INC],  g_w1rl[HIDC * INC];
__device__ unsigned short g_w2lh[OUTC * HIDC], g_w2ll[OUTC * HIDC];
__device__ unsigned short g_w2rh[OUTC * HIDC], g_w2rl[OUTC * HIDC];

__device__ __forceinline__ void split1(float v, unsigned short& h, unsigned short& l) {
    __nv_bfloat16 hb = __float2bfloat16_rn(v);
    float lo = v - __bfloat162float(hb);
    __nv_bfloat16 lb = __float2bfloat16_rn(lo);
    h = *(unsigned short*)&hb;
    l = *(unsigned short*)&lb;
}

// ---------------- init: zero degree histogram + detect edge dtype ----------------
__global__ void init_kernel(const void* __restrict__ ei_raw) {
    int stride = gridDim.x * blockDim.x;
    for (int i = blockIdx.x * blockDim.x + threadIdx.x; i < NN; i += stride)
        g_deg[i] = 0;
    if (blockIdx.x == 0 && threadIdx.x < 32) {
        const unsigned* w = (const unsigned*)ei_raw;
        unsigned acc = 0;
        for (int i = threadIdx.x; i < 128; i += 32) acc |= w[2 * i + 1];
        #pragma unroll
        for (int off = 16; off; off >>= 1) acc |= __shfl_xor_sync(0xFFFFFFFFu, acc, off);
        if (threadIdx.x == 0) g_is64 = (acc == 0) ? 1 : 0;
    }
}

__device__ __forceinline__ int load_edge(const void* ei_raw, long long idx, int is64) {
    if (is64) return (int)((const long long*)ei_raw)[idx];
    return ((const int*)ei_raw)[idx];
}

__global__ void hist_kernel(const void* __restrict__ ei_raw) {
    int is64 = g_is64;
    int i = blockIdx.x * blockDim.x + threadIdx.x;
    if (i >= EE) return;
    int dst = load_edge(ei_raw, (long long)EE + i, is64);
    atomicAdd(&g_deg[dst], 1);
}

// ---------------- multi-block exclusive scan over degrees ----------------
__global__ void scan_partial_kernel() {
    __shared__ int wsum[8];
    int b = blockIdx.x, t = threadIdx.x, lane = t & 31, w = t >> 5;
    int i = b * 256 + t;
    int v = (i < NN) ? g_deg[i] : 0;
    int x = v;
    #pragma unroll
    for (int off = 1; off < 32; off <<= 1) {
        int tmp = __shfl_up_sync(0xFFFFFFFFu, x, off);
        if (lane >= off) x += tmp;
    }
    if (lane == 31) wsum[w] = x;
    __syncthreads();
    if (w == 0 && lane < 8) {
        int s = wsum[lane];
        #pragma unroll
        for (int off = 1; off < 8; off <<= 1) {
            int tmp = __shfl_up_sync(0x000000FFu, s, off);
            if (lane >= off) s += tmp;
        }
        wsum[lane] = s;
    }
    __syncthreads();
    int incl = x + (w > 0 ? wsum[w - 1] : 0);
    if (i < NN) g_rowstart[i] = incl;   // temp: block-local inclusive
    if (t == 255) g_bsum[b] = incl;     // block total
}

__global__ void scan_bsum_kernel() {
    __shared__ int wsum[8];
    int t = threadIdx.x, lane = t & 31, w = t >> 5;
    const int NB = (NN + 255) / 256;
    int v = (t < NB) ? g_bsum[t] : 0;
    int x = v;
    #pragma unroll
    for (int off = 1; off < 32; off <<= 1) {
        int tmp = __shfl_up_sync(0xFFFFFFFFu, x, off);
        if (lane >= off) x += tmp;
    }
    if (lane == 31) wsum[w] = x;
    __syncthreads();
    if (w == 0 && lane < 8) {
        int s = wsum[lane];
        #pragma unroll
        for (int off = 1; off < 8; off <<= 1) {
            int tmp = __shfl_up_sync(0x000000FFu, s, off);
            if (lane >= off) s += tmp;
        }
        wsum[lane] = s;
    }
    __syncthreads();
    int incl = x + (w > 0 ? wsum[w - 1] : 0);
    if (t < NB) g_bsum[t] = incl;       // inclusive across blocks
}

__global__ void scan_write_kernel() {
    int b = blockIdx.x, t = threadIdx.x;
    int i = b * 256 + t;
    if (i < NN) {
        int off = (b > 0) ? g_bsum[b - 1] : 0;
        int excl = off + g_rowstart[i] - g_deg[i];
        g_rowstart[i] = excl;
        g_cursor[i]   = excl;
    }
    if (b == 0 && t == 0) g_rowstart[NN] = EE;
}

__global__ void fill_kernel(const void* __restrict__ ei_raw) {
    int is64 = g_is64;
    int i = blockIdx.x * blockDim.x + threadIdx.x;
    if (i >= EE) return;
    int src = load_edge(ei_raw, (long long)i, is64);
    int dst = load_edge(ei_raw, (long long)EE + i, is64);
    int p = atomicAdd(&g_cursor[dst], 1);
    g_col[p] = src;
}

// ---------------- weight / x splitting ----------------
__global__ void split_w_kernel(const float* __restrict__ W1l, const float* __restrict__ W1r,
                               const float* __restrict__ W2l, const float* __restrict__ W2r) {
    const int S = HIDC * INC;
    int i = blockIdx.x * blockDim.x + threadIdx.x;
    if (i < S)              split1(W1l[i], g_w1lh[i], g_w1ll[i]);
    else if (i < 2 * S)   { int j = i - S;     split1(W1r[j], g_w1rh[j], g_w1rl[j]); }
    else if (i < 3 * S)   { int j = i - 2 * S; split1(W2l[j], g_w2lh[j], g_w2ll[j]); }
    else if (i < 4 * S)   { int j = i - 3 * S; split1(W2r[j], g_w2rh[j], g_w2rl[j]); }
}

__global__ void split_x_kernel(const float* __restrict__ x) {
    int i = blockIdx.x * blockDim.x + threadIdx.x;  // float4 index
    if (i >= NN * INC / 4) return;
    float4 v = ((const float4*)x)[i];
    ushort4 hv, lv;
    split1(v.x, hv.x, lv.x); split1(v.y, hv.y, lv.y);
    split1(v.z, hv.z, lv.z); split1(v.w, hv.w, lv.w);
    ((ushort4*)g_xh)[i] = hv;
    ((ushort4*)g_xl)[i] = lv;
}

// ---------------- mean aggregation over 128-channel features -------------------
template <int MODE>
__global__ void agg128_kernel(const float* __restrict__ xin, float* __restrict__ outp) {
    const float* __restrict__ in = (MODE == 0) ? xin : (const float*)g_p;

    int warp = (blockIdx.x * blockDim.x + threadIdx.x) >> 5;
    if (warp >= NN) return;
    int lane = threadIdx.x & 31;

    int beg = g_rowstart[warp];
    int end = g_rowstart[warp + 1];
    float inv = 1.0f / (float)max(end - beg, 1);

    float4 acc0 = make_float4(0.f, 0.f, 0.f, 0.f);
    float4 acc1 = make_float4(0.f, 0.f, 0.f, 0.f);

    int j = beg;
    for (; j + 1 < end; j += 2) {
        int s0 = g_col[j];
        int s1 = g_col[j + 1];
        float4 t0 = __ldg((const float4*)(in + (size_t)s0 * 128) + lane);
        float4 t1 = __ldg((const float4*)(in + (size_t)s1 * 128) + lane);
        acc0.x += t0.x; acc0.y += t0.y; acc0.z += t0.z; acc0.w += t0.w;
        acc1.x += t1.x; acc1.y += t1.y; acc1.z += t1.z; acc1.w += t1.w;
    }
    if (j < end) {
        int s = g_col[j];
        float4 t = __ldg((const float4*)(in + (size_t)s * 128) + lane);
        acc0.x += t.x; acc0.y += t.y; acc0.z += t.z; acc0.w += t.w;
    }

    float4 r = make_float4((acc0.x + acc1.x) * inv, (acc0.y + acc1.y) * inv,
                           (acc0.z + acc1.z) * inv, (acc0.w + acc1.w) * inv);
    if (MODE == 0) {
        ushort4 hv, lv;
        split1(r.x, hv.x, lv.x); split1(r.y, hv.y, lv.y);
        split1(r.z, hv.z, lv.z); split1(r.w, hv.w, lv.w);
        ((ushort4*)g_m1h)[(size_t)warp * 32 + lane] = hv;
        ((ushort4*)g_m1l)[(size_t)warp * 32 + lane] = lv;
    } else {
        float4 qv = __ldg((const float4*)((const float*)g_q + (size_t)warp * 128) + lane);
        r.x += qv.x; r.y += qv.y; r.z += qv.z; r.w += qv.w;
        ((float4*)(outp + (size_t)warp * 128))[lane] = r;
    }
}

// ---------------- bf16 2-limb tensor-core GEMM (ldmatrix + double buffer) ------
__device__ __forceinline__ void mma_bf16(float c[4], const unsigned a[4], const unsigned b[2]) {
    asm volatile(
        "mma.sync.aligned.m16n8k16.row.col.f32.bf16.bf16.f32 "
        "{%0,%1,%2,%3},{%4,%5,%6,%7},{%8,%9},{%0,%1,%2,%3};"
        : "+f"(c[0]), "+f"(c[1]), "+f"(c[2]), "+f"(c[3])
        : "r"(a[0]), "r"(a[1]), "r"(a[2]), "r"(a[3]), "r"(b[0]), "r"(b[1]));
}

__device__ __forceinline__ void ldsm_x4(unsigned r[4], unsigned addr) {
    asm volatile("ldmatrix.sync.aligned.m8n8.x4.shared.b16 {%0,%1,%2,%3}, [%4];"
        : "=r"(r[0]), "=r"(r[1]), "=r"(r[2]), "=r"(r[3]) : "r"(addr));
}

#define S_LD   40                   // halves per row: 80B, 16B-aligned rows, conflict-free
#define PLANE  (128 * S_LD)         // halves per (stage, plane)
#define GSMEM  (8 * PLANE * 2)      // bytes: 4 planes x 2 stages

// MODE 0 (layer 1): grid (391,2): h-cols [by*128,+128) = relu(m1@W1l^T + x@W1r^T + b1)
//                   -> bf16 limb planes g_hh/g_hl
// MODE 1 (layer 2): grid (391,2): by==0: g_p = h@W2l^T ; by==1: g_q = h@W2r^T + b2
template <int K, int MODE>
__global__ void __launch_bounds__(256, 1)
gemm_bf16(const float* __restrict__ biasp) {
    extern __shared__ unsigned short sm[];
    unsigned short* Ah = sm;
    unsigned short* Al = Ah + 2 * PLANE;
    unsigned short* Bh = Al + 2 * PLANE;
    unsigned short* Bl = Bh + 2 * PLANE;

    const int t    = threadIdx.x;
    const int wid  = t >> 5;
    const int lane = t & 31;
    const int g    = lane >> 2;
    const int tig  = lane & 3;
    const int wm   = wid & 3;
    const int wn   = wid >> 2;
    const int row0 = blockIdx.x * 128;
    const int by   = blockIdx.y;

    // ldmatrix lane addressing
    const int a_row = (lane & 7) + ((lane >> 3) & 1) * 8;  // row within 16-row frag
    const int a_col = (lane >> 4) * 8;                     // 0 or 8 (k-half select)
    const unsigned uAh = (unsigned)__cvta_generic_to_shared(Ah);
    const unsigned uAl = (unsigned)__cvta_generic_to_shared(Al);
    const unsigned uBh = (unsigned)__cvta_generic_to_shared(Bh);
    const unsigned uBl = (unsigned)__cvta_generic_to_shared(Bl);

    float acc[2][8][4];
    #pragma unroll
    for (int im = 0; im < 2; im++)
        #pragma unroll
        for (int in_ = 0; in_ < 8; in_++)
            #pragma unroll
            for (int c = 0; c < 4; c++) acc[im][in_][c] = 0.f;

    const int TC = 8;  // both modes: 8 k-chunks of 32
    uint2 rah[4], ral[4], rbh[4], rbl[4];

    auto ldg_chunk = [&](int c) {
        const unsigned short *Aph, *Apl, *Wph, *Wpl;
        int wrow0, kk;
        if (MODE == 0) {
            int pass = c >> 2; kk = (c & 3) * 32;
            Aph = pass ? g_xh : g_m1h;   Apl = pass ? g_xl : g_m1l;
            Wph = pass ? g_w1rh : g_w1lh; Wpl = pass ? g_w1rl : g_w1ll;
            wrow0 = by * 128;
        } else {
            kk = c * 32;
            Aph = g_hh; Apl = g_hl;
            Wph = (by == 0) ? g_w2lh : g_w2rh;
            Wpl = (by == 0) ? g_w2ll : g_w2rl;
            wrow0 = 0;
        }
        #pragma unroll
        for (int u = 0; u < 4; u++) {
            int idx = t + u * 256;
            int row = idx >> 3;
            int c8  = (idx & 7) * 4;
            int r  = min(row0 + row, NN - 1);
            int wr = wrow0 + row;
            rah[u] = *(const uint2*)(Aph + (size_t)r * K + kk + c8);
            ral[u] = *(const uint2*)(Apl + (size_t)r * K + kk + c8);
            rbh[u] = *(const uint2*)(Wph + (size_t)wr * K + kk + c8);
            rbl[u] = *(const uint2*)(Wpl + (size_t)wr * K + kk + c8);
        }
    };

    auto sts_chunk = [&](int st) {
        #pragma unroll
        for (int u = 0; u < 4; u++) {
            int idx = t + u * 256;
            int row = idx >> 3;
            int c8  = (idx & 7) * 4;
            int o = st * PLANE + row * S_LD + c8;
            *(uint2*)&Ah[o] = rah[u];
            *(uint2*)&Al[o] = ral[u];
            *(uint2*)&Bh[o] = rbh[u];
            *(uint2*)&Bl[o] = rbl[u];
        }
    };

    auto compute = [&](int st) {
        const unsigned stoff = (unsigned)(st * PLANE) * 2u;
        #pragma unroll
        for (int o = 0; o < 32; o += 16) {
            unsigned ah[2][4], al[2][4], bh[8][2], bl[8][2];
            #pragma unroll
            for (int im = 0; im < 2; im++) {
                unsigned aoff = ((wm * 32 + im * 16 + a_row) * S_LD + o + a_col) * 2u + stoff;
                ldsm_x4(ah[im], uAh + aoff);
                ldsm_x4(al[im], uAl + aoff);
            }
            #pragma unroll
            for (int q = 0; q < 2; q++) {
                #pragma unroll
                for (int kh = 0; kh < 2; kh++) {
                    unsigned boff = ((wn * 64 + q * 32 + lane) * S_LD + o + kh * 8) * 2u + stoff;
                    unsigned r4[4];
                    ldsm_x4(r4, uBh + boff);
                    #pragma unroll
                    for (int j = 0; j < 4; j++) bh[q * 4 + j][kh] = r4[j];
                    ldsm_x4(r4, uBl + boff);
                    #pragma unroll
                    for (int j = 0; j < 4; j++) bl[q * 4 + j][kh] = r4[j];
                }
            }
            #pragma unroll
            for (int im = 0; im < 2; im++)
                #pragma unroll
                for (int in_ = 0; in_ < 8; in_++) {
                    mma_bf16(acc[im][in_], ah[im], bl[in_]);  // hi*lo
                    mma_bf16(acc[im][in_], al[im], bh[in_]);  // lo*hi
                    mma_bf16(acc[im][in_], ah[im], bh[in_]);  // hi*hi
                }
        }
    };

    // software pipeline: 2-stage, 1 sync per iteration
    ldg_chunk(0);
    sts_chunk(0);
    for (int c = 0; c < TC; c++) {
        __syncthreads();
        if (c + 1 < TC) ldg_chunk(c + 1);
        compute(c & 1);
        if (c + 1 < TC) sts_chunk((c + 1) & 1);
    }

    // epilogue
    const float* bias = (MODE == 0) ? biasp : ((by == 1) ? biasp : nullptr);
    const int outcol0 = (MODE == 0) ? by * 128 : 0;
    #pragma unroll
    for (int im = 0; im < 2; im++) {
        #pragma unroll
        for (int in_ = 0; in_ < 8; in_++) {
            int col  = wn * 64 + in_ * 8 + 2 * tig;
            int gcol = outcol0 + col;
            float bx = 0.f, byv = 0.f;
            if (bias) { bx = __ldg(bias + gcol); byv = __ldg(bias + gcol + 1); }
            int r0 = row0 + wm * 32 + im * 16 + g;
            #pragma unroll
            for (int half = 0; half < 2; half++) {
                int r = r0 + half * 8;
                if (r >= NN) continue;
                float vx = acc[im][in_][2 * half + 0] + bx;
                float vy = acc[im][in_][2 * half + 1] + byv;
                if (MODE == 0) {
                    vx = fmaxf(vx, 0.f); vy = fmaxf(vy, 0.f);
                    unsigned short hx, lx, hy, ly;
                    split1(vx, hx, lx); split1(vy, hy, ly);
                    *(unsigned*)&g_hh[(size_t)r * HIDC + gcol] = (unsigned)hx | ((unsigned)hy << 16);
                    *(unsigned*)&g_hl[(size_t)r * HIDC + gcol] = (unsigned)lx | ((unsigned)ly << 16);
                } else {
                    float* out = (by == 0) ? g_p : g_q;
                    *(float2*)(out + (size_t)r * OUTC + col) = make_float2(vx, vy);
                }
            }
        }
    }
}

// ---------------- launch ----------------
extern "C" void kernel_launch(void* const* d_in, const int* in_sizes, int n_in,
                              void* d_out, int out_size) {
    const float* x   = (const float*)d_in[0];
    const void*  ei  = d_in[1];
    const float* W1l = (const float*)d_in[2];
    const float* b1  = (const float*)d_in[3];
    const float* W1r = (const float*)d_in[4];
    const float* W2l = (const float*)d_in[5];
    const float* b2  = (const float*)d_in[6];
    const float* W2r = (const float*)d_in[7];
    float* out = (float*)d_out;

    cudaFuncSetAttribute(gemm_bf16<INC, 0>,
                         cudaFuncAttributeMaxDynamicSharedMemorySize, GSMEM);
    cudaFuncSetAttribute(gemm_bf16<HIDC, 1>,
                         cudaFuncAttributeMaxDynamicSharedMemorySize, GSMEM);

    const int NB = (NN + 255) / 256;  // 196

    // CSR build
    init_kernel<<<196, 256>>>(ei);
    hist_kernel<<<(EE + 255) / 256, 256>>>(ei);
    scan_partial_kernel<<<NB, 256>>>();
    scan_bsum_kernel<<<1, 256>>>();
    scan_write_kernel<<<NB, 256>>>();
    fill_kernel<<<(EE + 255) / 256, 256>>>(ei);

    // operand limb splits
    split_w_kernel<<<(4 * HIDC * INC + 255) / 256, 256>>>(W1l, W1r, W2l, W2r);
    split_x_kernel<<<(NN * INC / 4 + 255) / 256, 256>>>(x);

    // layer 1: m1 = agg(x);  h = relu(m1@W1l^T + x@W1r^T + b1)  (bf16 limb planes)
    agg128_kernel<0><<<(NN + 7) / 8, 256>>>(x, nullptr);
    gemm_bf16<INC, 0><<<dim3((NN + 127) / 128, 2), 256, GSMEM>>>(b1);

    // layer 2: p = h@W2l^T; q = h@W2r^T + b2;  out = agg(p) + q
    gemm_bf16<HIDC, 1><<<dim3((NN + 127) / 128, 2), 256, GSMEM>>>(b2);
    agg128_kernel<1><<<(NN + 7) / 8, 256>>>(nullptr, out);
}

// round 15
// speedup vs baseline: 2.7369x; 1.1592x over previous
#include <cuda_runtime.h>
#include <cuda_bf16.h>
#include <cstdint>

// Problem constants
#define NN   50000
#define EE   800000
#define INC  128
#define HIDC 256
#define OUTC 128

// ---------------- device scratch (static globals; no allocation) ----------------
__device__ int   g_deg[NN];
__device__ int   g_rowstart[NN + 1];
__device__ int   g_cursor[NN];
__device__ int   g_col[EE];
__device__ int   g_is64;
__device__ int   g_bsum[256];

// bf16 limb planes (hi/lo) for GEMM operands (16B aligned for cp.async)
__device__ __align__(16) unsigned short g_xh [(size_t)NN * INC],  g_xl [(size_t)NN * INC];
__device__ __align__(16) unsigned short g_m1h[(size_t)NN * INC],  g_m1l[(size_t)NN * INC];
__device__ __align__(16) unsigned short g_hh [(size_t)NN * HIDC], g_hl [(size_t)NN * HIDC];
__device__ float g_p[(size_t)NN * OUTC];   // p = h @ W2l^T
__device__ float g_q[(size_t)NN * OUTC];   // q = h @ W2r^T + b2

// weight limb planes
__device__ __align__(16) unsigned short g_w1lh[HIDC * INC],  g_w1ll[HIDC * INC];
__device__ __align__(16) unsigned short g_w1rh[HIDC * INC],  g_w1rl[HIDC * INC];
__device__ __align__(16) unsigned short g_w2lh[OUTC * HIDC], g_w2ll[OUTC * HIDC];
__device__ __align__(16) unsigned short g_w2rh[OUTC * HIDC], g_w2rl[OUTC * HIDC];

__device__ __forceinline__ void split1(float v, unsigned short& h, unsigned short& l) {
    __nv_bfloat16 hb = __float2bfloat16_rn(v);
    float lo = v - __bfloat162float(hb);
    __nv_bfloat16 lb = __float2bfloat16_rn(lo);
    h = *(unsigned short*)&hb;
    l = *(unsigned short*)&lb;
}

// ---------------- init: zero degree histogram + detect edge dtype ----------------
__global__ void init_kernel(const void* __restrict__ ei_raw) {
    int stride = gridDim.x * blockDim.x;
    for (int i = blockIdx.x * blockDim.x + threadIdx.x; i < NN; i += stride)
        g_deg[i] = 0;
    if (blockIdx.x == 0 && threadIdx.x < 32) {
        const unsigned* w = (const unsigned*)ei_raw;
        unsigned acc = 0;
        for (int i = threadIdx.x; i < 128; i += 32) acc |= w[2 * i + 1];
        #pragma unroll
        for (int off = 16; off; off >>= 1) acc |= __shfl_xor_sync(0xFFFFFFFFu, acc, off);
        if (threadIdx.x == 0) g_is64 = (acc == 0) ? 1 : 0;
    }
}

__device__ __forceinline__ int load_edge(const void* ei_raw, long long idx, int is64) {
    if (is64) return (int)((const long long*)ei_raw)[idx];
    return ((const int*)ei_raw)[idx];
}

__global__ void hist_kernel(const void* __restrict__ ei_raw) {
    int is64 = g_is64;
    int i = blockIdx.x * blockDim.x + threadIdx.x;
    if (i >= EE) return;
    int dst = load_edge(ei_raw, (long long)EE + i, is64);
    atomicAdd(&g_deg[dst], 1);
}

// ---------------- multi-block exclusive scan over degrees ----------------
__global__ void scan_partial_kernel() {
    __shared__ int wsum[8];
    int b = blockIdx.x, t = threadIdx.x, lane = t & 31, w = t >> 5;
    int i = b * 256 + t;
    int v = (i < NN) ? g_deg[i] : 0;
    int x = v;
    #pragma unroll
    for (int off = 1; off < 32; off <<= 1) {
        int tmp = __shfl_up_sync(0xFFFFFFFFu, x, off);
        if (lane >= off) x += tmp;
    }
    if (lane == 31) wsum[w] = x;
    __syncthreads();
    if (w == 0 && lane < 8) {
        int s = wsum[lane];
        #pragma unroll
        for (int off = 1; off < 8; off <<= 1) {
            int tmp = __shfl_up_sync(0x000000FFu, s, off);
            if (lane >= off) s += tmp;
        }
        wsum[lane] = s;
    }
    __syncthreads();
    int incl = x + (w > 0 ? wsum[w - 1] : 0);
    if (i < NN) g_rowstart[i] = incl;
    if (t == 255) g_bsum[b] = incl;
}

__global__ void scan_bsum_kernel() {
    __shared__ int wsum[8];
    int t = threadIdx.x, lane = t & 31, w = t >> 5;
    const int NB = (NN + 255) / 256;
    int v = (t < NB) ? g_bsum[t] : 0;
    int x = v;
    #pragma unroll
    for (int off = 1; off < 32; off <<= 1) {
        int tmp = __shfl_up_sync(0xFFFFFFFFu, x, off);
        if (lane >= off) x += tmp;
    }
    if (lane == 31) wsum[w] = x;
    __syncthreads();
    if (w == 0 && lane < 8) {
        int s = wsum[lane];
        #pragma unroll
        for (int off = 1; off < 8; off <<= 1) {
            int tmp = __shfl_up_sync(0x000000FFu, s, off);
            if (lane >= off) s += tmp;
        }
        wsum[lane] = s;
    }
    __syncthreads();
    int incl = x + (w > 0 ? wsum[w - 1] : 0);
    if (t < NB) g_bsum[t] = incl;
}

__global__ void scan_write_kernel() {
    int b = blockIdx.x, t = threadIdx.x;
    int i = b * 256 + t;
    if (i < NN) {
        int off = (b > 0) ? g_bsum[b - 1] : 0;
        int excl = off + g_rowstart[i] - g_deg[i];
        g_rowstart[i] = excl;
        g_cursor[i]   = excl;
    }
    if (b == 0 && t == 0) g_rowstart[NN] = EE;
}

__global__ void fill_kernel(const void* __restrict__ ei_raw) {
    int is64 = g_is64;
    int i = blockIdx.x * blockDim.x + threadIdx.x;
    if (i >= EE) return;
    int src = load_edge(ei_raw, (long long)i, is64);
    int dst = load_edge(ei_raw, (long long)EE + i, is64);
    int p = atomicAdd(&g_cursor[dst], 1);
    g_col[p] = src;
}

// ---------------- weight / x splitting ----------------
__global__ void split_w_kernel(const float* __restrict__ W1l, const float* __restrict__ W1r,
                               const float* __restrict__ W2l, const float* __restrict__ W2r) {
    const int S = HIDC * INC;
    int i = blockIdx.x * blockDim.x + threadIdx.x;
    if (i < S)              split1(W1l[i], g_w1lh[i], g_w1ll[i]);
    else if (i < 2 * S)   { int j = i - S;     split1(W1r[j], g_w1rh[j], g_w1rl[j]); }
    else if (i < 3 * S)   { int j = i - 2 * S; split1(W2l[j], g_w2lh[j], g_w2ll[j]); }
    else if (i < 4 * S)   { int j = i - 3 * S; split1(W2r[j], g_w2rh[j], g_w2rl[j]); }
}

__global__ void split_x_kernel(const float* __restrict__ x) {
    int i = blockIdx.x * blockDim.x + threadIdx.x;
    if (i >= NN * INC / 4) return;
    float4 v = ((const float4*)x)[i];
    ushort4 hv, lv;
    split1(v.x, hv.x, lv.x); split1(v.y, hv.y, lv.y);
    split1(v.z, hv.z, lv.z); split1(v.w, hv.w, lv.w);
    ((ushort4*)g_xh)[i] = hv;
    ((ushort4*)g_xl)[i] = lv;
}

// ---------------- mean aggregation over 128-channel features -------------------
template <int MODE>
__global__ void agg128_kernel(const float* __restrict__ xin, float* __restrict__ outp) {
    const float* __restrict__ in = (MODE == 0) ? xin : (const float*)g_p;

    int warp = (blockIdx.x * blockDim.x + threadIdx.x) >> 5;
    if (warp >= NN) return;
    int lane = threadIdx.x & 31;

    int beg = g_rowstart[warp];
    int end = g_rowstart[warp + 1];
    float inv = 1.0f / (float)max(end - beg, 1);

    float4 acc0 = make_float4(0.f, 0.f, 0.f, 0.f);
    float4 acc1 = make_float4(0.f, 0.f, 0.f, 0.f);

    int j = beg;
    for (; j + 1 < end; j += 2) {
        int s0 = g_col[j];
        int s1 = g_col[j + 1];
        float4 t0 = __ldg((const float4*)(in + (size_t)s0 * 128) + lane);
        float4 t1 = __ldg((const float4*)(in + (size_t)s1 * 128) + lane);
        acc0.x += t0.x; acc0.y += t0.y; acc0.z += t0.z; acc0.w += t0.w;
        acc1.x += t1.x; acc1.y += t1.y; acc1.z += t1.z; acc1.w += t1.w;
    }
    if (j < end) {
        int s = g_col[j];
        float4 t = __ldg((const float4*)(in + (size_t)s * 128) + lane);
        acc0.x += t.x; acc0.y += t.y; acc0.z += t.z; acc0.w += t.w;
    }

    float4 r = make_float4((acc0.x + acc1.x) * inv, (acc0.y + acc1.y) * inv,
                           (acc0.z + acc1.z) * inv, (acc0.w + acc1.w) * inv);
    if (MODE == 0) {
        ushort4 hv, lv;
        split1(r.x, hv.x, lv.x); split1(r.y, hv.y, lv.y);
        split1(r.z, hv.z, lv.z); split1(r.w, hv.w, lv.w);
        ((ushort4*)g_m1h)[(size_t)warp * 32 + lane] = hv;
        ((ushort4*)g_m1l)[(size_t)warp * 32 + lane] = lv;
    } else {
        float4 qv = __ldg((const float4*)((const float*)g_q + (size_t)warp * 128) + lane);
        r.x += qv.x; r.y += qv.y; r.z += qv.z; r.w += qv.w;
        ((float4*)(outp + (size_t)warp * 128))[lane] = r;
    }
}

// ---------------- bf16 2-limb tensor-core GEMM (ldmatrix + cp.async pipeline) --
__device__ __forceinline__ void mma_bf16(float c[4], const unsigned a[4], const unsigned b[2]) {
    asm volatile(
        "mma.sync.aligned.m16n8k16.row.col.f32.bf16.bf16.f32 "
        "{%0,%1,%2,%3},{%4,%5,%6,%7},{%8,%9},{%0,%1,%2,%3};"
        : "+f"(c[0]), "+f"(c[1]), "+f"(c[2]), "+f"(c[3])
        : "r"(a[0]), "r"(a[1]), "r"(a[2]), "r"(a[3]), "r"(b[0]), "r"(b[1]));
}

__device__ __forceinline__ void ldsm_x4(unsigned r[4], unsigned addr) {
    asm volatile("ldmatrix.sync.aligned.m8n8.x4.shared.b16 {%0,%1,%2,%3}, [%4];"
        : "=r"(r[0]), "=r"(r[1]), "=r"(r[2]), "=r"(r[3]) : "r"(addr));
}

__device__ __forceinline__ void cpa16(unsigned smem, const void* g) {
    asm volatile("cp.async.cg.shared.global [%0], [%1], 16;" :: "r"(smem), "l"(g));
}

#define S_LD   40                   // halves per row: 80B rows, 16B-aligned, conflict-free
#define PLANE  (128 * S_LD)         // halves per (stage, plane)
#define GSMEM  (8 * PLANE * 2)      // bytes: 4 planes x 2 stages = 80KB

// MODE 0 (layer 1): grid (391,2): h-cols [by*128,+128) = relu(m1@W1l^T + x@W1r^T + b1)
//                   -> bf16 limb planes g_hh/g_hl
// MODE 1 (layer 2): grid (391,2): by==0: g_p = h@W2l^T ; by==1: g_q = h@W2r^T + b2
template <int K, int MODE>
__global__ void __launch_bounds__(256)
gemm_bf16(const float* __restrict__ biasp) {
    extern __shared__ unsigned short sm[];
    unsigned short* Ah = sm;
    unsigned short* Al = Ah + 2 * PLANE;
    unsigned short* Bh = Al + 2 * PLANE;
    unsigned short* Bl = Bh + 2 * PLANE;

    const int t    = threadIdx.x;
    const int wid  = t >> 5;
    const int lane = t & 31;
    const int g    = lane >> 2;
    const int tig  = lane & 3;
    const int wm   = wid & 3;
    const int wn   = wid >> 2;
    const int row0 = blockIdx.x * 128;
    const int by   = blockIdx.y;

    // ldmatrix lane addressing
    const int a_row = (lane & 7) + ((lane >> 3) & 1) * 8;
    const int a_col = (lane >> 4) * 8;
    const unsigned uAh = (unsigned)__cvta_generic_to_shared(Ah);
    const unsigned uAl = (unsigned)__cvta_generic_to_shared(Al);
    const unsigned uBh = (unsigned)__cvta_generic_to_shared(Bh);
    const unsigned uBl = (unsigned)__cvta_generic_to_shared(Bl);

    float acc[2][8][4];
    #pragma unroll
    for (int im = 0; im < 2; im++)
        #pragma unroll
        for (int in_ = 0; in_ < 8; in_++)
            #pragma unroll
            for (int c = 0; c < 4; c++) acc[im][in_][c] = 0.f;

    const int TC = 8;  // 8 k-chunks of 32

    // async-copy one chunk's 4 plane tiles into stage st
    auto copy_chunk = [&](int c, int st) {
        const unsigned short *Aph, *Apl, *Wph, *Wpl;
        int wrow0, kk;
        if (MODE == 0) {
            int pass = c >> 2; kk = (c & 3) * 32;
            Aph = pass ? g_xh : g_m1h;   Apl = pass ? g_xl : g_m1l;
            Wph = pass ? g_w1rh : g_w1lh; Wpl = pass ? g_w1rl : g_w1ll;
            wrow0 = by * 128;
        } else {
            kk = c * 32;
            Aph = g_hh; Apl = g_hl;
            Wph = (by == 0) ? g_w2lh : g_w2rh;
            Wpl = (by == 0) ? g_w2ll : g_w2rl;
            wrow0 = 0;
        }
        // 128 rows x 4 uint4-per-row = 512 items per plane; 256 threads x u<2
        #pragma unroll
        for (int u = 0; u < 2; u++) {
            int idx = t + u * 256;
            int row = idx >> 2;
            int c16 = idx & 3;                       // 16B unit within 64B of k-chunk
            int r  = min(row0 + row, NN - 1);
            int wr = wrow0 + row;
            unsigned so = (unsigned)(st * PLANE + row * S_LD) * 2u + (unsigned)c16 * 16u;
            cpa16(uAh + so, Aph + (size_t)r * K + kk + c16 * 8);
            cpa16(uAl + so, Apl + (size_t)r * K + kk + c16 * 8);
            cpa16(uBh + so, Wph + (size_t)wr * K + kk + c16 * 8);
            cpa16(uBl + so, Wpl + (size_t)wr * K + kk + c16 * 8);
        }
        asm volatile("cp.async.commit_group;" ::: "memory");
    };

    auto compute = [&](int st) {
        const unsigned stoff = (unsigned)(st * PLANE) * 2u;
        #pragma unroll
        for (int o = 0; o < 32; o += 16) {
            unsigned ah[2][4], al[2][4], bh[8][2], bl[8][2];
            #pragma unroll
            for (int im = 0; im < 2; im++) {
                unsigned aoff = ((wm * 32 + im * 16 + a_row) * S_LD + o + a_col) * 2u + stoff;
                ldsm_x4(ah[im], uAh + aoff);
                ldsm_x4(al[im], uAl + aoff);
            }
            #pragma unroll
            for (int q = 0; q < 2; q++) {
                #pragma unroll
                for (int kh = 0; kh < 2; kh++) {
                    unsigned boff = ((wn * 64 + q * 32 + lane) * S_LD + o + kh * 8) * 2u + stoff;
                    unsigned r4[4];
                    ldsm_x4(r4, uBh + boff);
                    #pragma unroll
                    for (int j = 0; j < 4; j++) bh[q * 4 + j][kh] = r4[j];
                    ldsm_x4(r4, uBl + boff);
                    #pragma unroll
                    for (int j = 0; j < 4; j++) bl[q * 4 + j][kh] = r4[j];
                }
            }
            #pragma unroll
            for (int im = 0; im < 2; im++)
                #pragma unroll
                for (int in_ = 0; in_ < 8; in_++) {
                    mma_bf16(acc[im][in_], ah[im], bl[in_]);  // hi*lo
                    mma_bf16(acc[im][in_], al[im], bh[in_]);  // lo*hi
                    mma_bf16(acc[im][in_], ah[im], bh[in_]);  // hi*hi
                }
        }
    };

    // 2-stage cp.async pipeline
    copy_chunk(0, 0);
    for (int c = 0; c < TC; c++) {
        if (c + 1 < TC) {
            copy_chunk(c + 1, (c + 1) & 1);
            asm volatile("cp.async.wait_group 1;" ::: "memory");
        } else {
            asm volatile("cp.async.wait_group 0;" ::: "memory");
        }
        __syncthreads();          // stage c&1 visible to all warps
        compute(c & 1);
        __syncthreads();          // stage c&1 fully consumed before reuse
    }

    // epilogue
    const float* bias = (MODE == 0) ? biasp : ((by == 1) ? biasp : nullptr);
    const int outcol0 = (MODE == 0) ? by * 128 : 0;
    #pragma unroll
    for (int im = 0; im < 2; im++) {
        #pragma unroll
        for (int in_ = 0; in_ < 8; in_++) {
            int col  = wn * 64 + in_ * 8 + 2 * tig;
            int gcol = outcol0 + col;
            float bx = 0.f, byv = 0.f;
            if (bias) { bx = __ldg(bias + gcol); byv = __ldg(bias + gcol + 1); }
            int r0 = row0 + wm * 32 + im * 16 + g;
            #pragma unroll
            for (int half = 0; half < 2; half++) {
                int r = r0 + half * 8;
                if (r >= NN) continue;
                float vx = acc[im][in_][2 * half + 0] + bx;
                float vy = acc[im][in_][2 * half + 1] + byv;
                if (MODE == 0) {
                    vx = fmaxf(vx, 0.f); vy = fmaxf(vy, 0.f);
                    unsigned short hx, lx, hy, ly;
                    split1(vx, hx, lx); split1(vy, hy, ly);
                    *(unsigned*)&g_hh[(size_t)r * HIDC + gcol] = (unsigned)hx | ((unsigned)hy << 16);
                    *(unsigned*)&g_hl[(size_t)r * HIDC + gcol] = (unsigned)lx | ((unsigned)ly << 16);
                } else {
                    float* out = (by == 0) ? g_p : g_q;
                    *(float2*)(out + (size_t)r * OUTC + col) = make_float2(vx, vy);
                }
            }
        }
    }
}

// ---------------- launch ----------------
extern "C" void kernel_launch(void* const* d_in, const int* in_sizes, int n_in,
                              void* d_out, int out_size) {
    const float* x   = (const float*)d_in[0];
    const void*  ei  = d_in[1];
    const float* W1l = (const float*)d_in[2];
    const float* b1  = (const float*)d_in[3];
    const float* W1r = (const float*)d_in[4];
    const float* W2l = (const float*)d_in[5];
    const float* b2  = (const float*)d_in[6];
    const float* W2r = (const float*)d_in[7];
    float* out = (float*)d_out;

    cudaFuncSetAttribute(gemm_bf16<INC, 0>,
                         cudaFuncAttributeMaxDynamicSharedMemorySize, GSMEM);
    cudaFuncSetAttribute(gemm_bf16<HIDC, 1>,
                         cudaFuncAttributeMaxDynamicSharedMemorySize, GSMEM);

    const int NB = (NN + 255) / 256;  // 196

    // CSR build
    init_kernel<<<196, 256>>>(ei);
    hist_kernel<<<(EE + 255) / 256, 256>>>(ei);
    scan_partial_kernel<<<NB, 256>>>();
    scan_bsum_kernel<<<1, 256>>>();
    scan_write_kernel<<<NB, 256>>>();
    fill_kernel<<<(EE + 255) / 256, 256>>>(ei);

    // operand limb splits
    split_w_kernel<<<(4 * HIDC * INC + 255) / 256, 256>>>(W1l, W1r, W2l, W2r);
    split_x_kernel<<<(NN * INC / 4 + 255) / 256, 256>>>(x);

    // layer 1: m1 = agg(x);  h = relu(m1@W1l^T + x@W1r^T + b1)  (bf16 limb planes)
    agg128_kernel<0><<<(NN + 7) / 8, 256>>>(x, nullptr);
    gemm_bf16<INC, 0><<<dim3((NN + 127) / 128, 2), 256, GSMEM>>>(b1);

    // layer 2: p = h@W2l^T; q = h@W2r^T + b2;  out = agg(p) + q
    gemm_bf16<HIDC, 1><<<dim3((NN + 127) / 128, 2), 256, GSMEM>>>(b2);
    agg128_kernel<1><<<(NN + 7) / 8, 256>>>(nullptr, out);
}

// round 16
// speedup vs baseline: 3.0358x; 1.1092x over previous
#include <cuda_runtime.h>
#include <cuda_bf16.h>
#include <cuda_fp16.h>
#include <cstdint>

// Problem constants
#define NN   50000
#define EE   800000
#define INC  128
#define HIDC 256
#define OUTC 128

// ---------------- device scratch (static globals; no allocation) ----------------
__device__ int   g_deg[NN];
__device__ int   g_rowstart[NN + 1];
__device__ int   g_cursor[NN];
__device__ int   g_col[EE];
__device__ int   g_is64;
__device__ int   g_bsum[256];

// bf16 limb planes (hi/lo) for GEMM operands (16B aligned for cp.async)
__device__ __align__(16) unsigned short g_xh [(size_t)NN * INC],  g_xl [(size_t)NN * INC];
__device__ __align__(16) unsigned short g_m1h[(size_t)NN * INC],  g_m1l[(size_t)NN * INC];
__device__ __align__(16) unsigned short g_hh [(size_t)NN * HIDC], g_hl [(size_t)NN * HIDC];
// fp16 gather operands for aggregation
__device__ __align__(16) unsigned short g_xf16[(size_t)NN * INC];
__device__ __align__(16) unsigned short g_pf16[(size_t)NN * OUTC];  // p = h @ W2l^T (fp16)
__device__ float g_q[(size_t)NN * OUTC];   // q = h @ W2r^T + b2 (fp32)

// weight limb planes
__device__ __align__(16) unsigned short g_w1lh[HIDC * INC],  g_w1ll[HIDC * INC];
__device__ __align__(16) unsigned short g_w1rh[HIDC * INC],  g_w1rl[HIDC * INC];
__device__ __align__(16) unsigned short g_w2lh[OUTC * HIDC], g_w2ll[OUTC * HIDC];
__device__ __align__(16) unsigned short g_w2rh[OUTC * HIDC], g_w2rl[OUTC * HIDC];

__device__ __forceinline__ void split1(float v, unsigned short& h, unsigned short& l) {
    __nv_bfloat16 hb = __float2bfloat16_rn(v);
    float lo = v - __bfloat162float(hb);
    __nv_bfloat16 lb = __float2bfloat16_rn(lo);
    h = *(unsigned short*)&hb;
    l = *(unsigned short*)&lb;
}

__device__ __forceinline__ int load_edge(const void* ei_raw, long long idx, int is64) {
    if (is64) return (int)((const long long*)ei_raw)[idx];
    return ((const int*)ei_raw)[idx];
}

// ---------------- fused prep: weight splits | x split(+fp16) | deg zero + dtype --
#define SWBLK 512     // 4*HIDC*INC/256
#define SXBLK 6250    // NN*INC/4/256
__global__ void prep_kernel(const void* __restrict__ ei_raw, const float* __restrict__ x,
                            const float* __restrict__ W1l, const float* __restrict__ W1r,
                            const float* __restrict__ W2l, const float* __restrict__ W2r) {
    int b = blockIdx.x, t = threadIdx.x;
    if (b < SWBLK) {
        const int S = HIDC * INC;
        int i = b * 256 + t;
        if (i < S)            split1(W1l[i], g_w1lh[i], g_w1ll[i]);
        else if (i < 2 * S) { int j = i - S;     split1(W1r[j], g_w1rh[j], g_w1rl[j]); }
        else if (i < 3 * S) { int j = i - 2 * S; split1(W2l[j], g_w2lh[j], g_w2ll[j]); }
        else                { int j = i - 3 * S; split1(W2r[j], g_w2rh[j], g_w2rl[j]); }
    } else if (b < SWBLK + SXBLK) {
        int i = (b - SWBLK) * 256 + t;          // float4 index
        if (i < NN * INC / 4) {
            float4 v = ((const float4*)x)[i];
            ushort4 hv, lv;
            split1(v.x, hv.x, lv.x); split1(v.y, hv.y, lv.y);
            split1(v.z, hv.z, lv.z); split1(v.w, hv.w, lv.w);
            ((ushort4*)g_xh)[i] = hv;
            ((ushort4*)g_xl)[i] = lv;
            __half2 f01 = __floats2half2_rn(v.x, v.y);
            __half2 f23 = __floats2half2_rn(v.z, v.w);
            uint2 fv;
            fv.x = *(unsigned*)&f01; fv.y = *(unsigned*)&f23;
            ((uint2*)g_xf16)[i] = fv;
        }
    } else {
        int bb = b - SWBLK - SXBLK;
        int i = bb * 256 + t;
        if (i < NN) g_deg[i] = 0;
        if (bb == 0 && t < 32) {
            const unsigned* w = (const unsigned*)ei_raw;
            unsigned acc = 0;
            for (int i2 = t; i2 < 128; i2 += 32) acc |= w[2 * i2 + 1];
            #pragma unroll
            for (int off = 16; off; off >>= 1) acc |= __shfl_xor_sync(0xFFFFFFFFu, acc, off);
            if (t == 0) g_is64 = (acc == 0) ? 1 : 0;
        }
    }
}

__global__ void hist_kernel(const void* __restrict__ ei_raw) {
    int is64 = g_is64;
    int i = blockIdx.x * blockDim.x + threadIdx.x;
    if (i >= EE) return;
    int dst = load_edge(ei_raw, (long long)EE + i, is64);
    atomicAdd(&g_deg[dst], 1);
}

// ---------------- multi-block exclusive scan over degrees ----------------
__global__ void scan_partial_kernel() {
    __shared__ int wsum[8];
    int b = blockIdx.x, t = threadIdx.x, lane = t & 31, w = t >> 5;
    int i = b * 256 + t;
    int v = (i < NN) ? g_deg[i] : 0;
    int x = v;
    #pragma unroll
    for (int off = 1; off < 32; off <<= 1) {
        int tmp = __shfl_up_sync(0xFFFFFFFFu, x, off);
        if (lane >= off) x += tmp;
    }
    if (lane == 31) wsum[w] = x;
    __syncthreads();
    if (w == 0 && lane < 8) {
        int s = wsum[lane];
        #pragma unroll
        for (int off = 1; off < 8; off <<= 1) {
            int tmp = __shfl_up_sync(0x000000FFu, s, off);
            if (lane >= off) s += tmp;
        }
        wsum[lane] = s;
    }
    __syncthreads();
    int incl = x + (w > 0 ? wsum[w - 1] : 0);
    if (i < NN) g_rowstart[i] = incl;
    if (t == 255) g_bsum[b] = incl;
}

__global__ void scan_bsum_kernel() {
    __shared__ int wsum[8];
    int t = threadIdx.x, lane = t & 31, w = t >> 5;
    const int NB = (NN + 255) / 256;
    int v = (t < NB) ? g_bsum[t] : 0;
    int x = v;
    #pragma unroll
    for (int off = 1; off < 32; off <<= 1) {
        int tmp = __shfl_up_sync(0xFFFFFFFFu, x, off);
        if (lane >= off) x += tmp;
    }
    if (lane == 31) wsum[w] = x;
    __syncthreads();
    if (w == 0 && lane < 8) {
        int s = wsum[lane];
        #pragma unroll
        for (int off = 1; off < 8; off <<= 1) {
            int tmp = __shfl_up_sync(0x000000FFu, s, off);
            if (lane >= off) s += tmp;
        }
        wsum[lane] = s;
    }
    __syncthreads();
    int incl = x + (w > 0 ? wsum[w - 1] : 0);
    if (t < NB) g_bsum[t] = incl;
}

__global__ void scan_write_kernel() {
    int b = blockIdx.x, t = threadIdx.x;
    int i = b * 256 + t;
    if (i < NN) {
        int off = (b > 0) ? g_bsum[b - 1] : 0;
        int excl = off + g_rowstart[i] - g_deg[i];
        g_rowstart[i] = excl;
        g_cursor[i]   = excl;
    }
    if (b == 0 && t == 0) g_rowstart[NN] = EE;
}

__global__ void fill_kernel(const void* __restrict__ ei_raw) {
    int is64 = g_is64;
    int i = blockIdx.x * blockDim.x + threadIdx.x;
    if (i >= EE) return;
    int src = load_edge(ei_raw, (long long)i, is64);
    int dst = load_edge(ei_raw, (long long)EE + i, is64);
    int p = atomicAdd(&g_cursor[dst], 1);
    g_col[p] = src;
}

// ---------------- mean aggregation over 128-channel fp16 features --------------
// MODE 0: m1 = mean_agg(g_xf16) -> bf16 limb planes
// MODE 1: out = mean_agg(g_pf16) + g_q  (fp32, final output)
template <int MODE>
__global__ void agg128_kernel(float* __restrict__ outp) {
    const unsigned short* __restrict__ in = (MODE == 0) ? g_xf16 : g_pf16;

    int warp = (blockIdx.x * blockDim.x + threadIdx.x) >> 5;
    if (warp >= NN) return;
    int lane = threadIdx.x & 31;

    int beg = g_rowstart[warp];
    int end = g_rowstart[warp + 1];
    float inv = 1.0f / (float)max(end - beg, 1);

    float4 acc0 = make_float4(0.f, 0.f, 0.f, 0.f);
    float4 acc1 = make_float4(0.f, 0.f, 0.f, 0.f);
    float4 acc2 = make_float4(0.f, 0.f, 0.f, 0.f);
    float4 acc3 = make_float4(0.f, 0.f, 0.f, 0.f);

    auto accum = [&](float4& a, uint2 v) {
        float2 f0 = __half22float2(*(__half2*)&v.x);
        float2 f1 = __half22float2(*(__half2*)&v.y);
        a.x += f0.x; a.y += f0.y; a.z += f1.x; a.w += f1.y;
    };

    int j = beg;
    for (; j + 3 < end; j += 4) {
        int s0 = g_col[j],     s1 = g_col[j + 1];
        int s2 = g_col[j + 2], s3 = g_col[j + 3];
        uint2 v0 = __ldg((const uint2*)(in + (size_t)s0 * 128) + lane);
        uint2 v1 = __ldg((const uint2*)(in + (size_t)s1 * 128) + lane);
        uint2 v2 = __ldg((const uint2*)(in + (size_t)s2 * 128) + lane);
        uint2 v3 = __ldg((const uint2*)(in + (size_t)s3 * 128) + lane);
        accum(acc0, v0); accum(acc1, v1); accum(acc2, v2); accum(acc3, v3);
    }
    for (; j < end; j++) {
        int s = g_col[j];
        uint2 v = __ldg((const uint2*)(in + (size_t)s * 128) + lane);
        accum(acc0, v);
    }

    float4 r;
    r.x = (acc0.x + acc1.x + acc2.x + acc3.x) * inv;
    r.y = (acc0.y + acc1.y + acc2.y + acc3.y) * inv;
    r.z = (acc0.z + acc1.z + acc2.z + acc3.z) * inv;
    r.w = (acc0.w + acc1.w + acc2.w + acc3.w) * inv;

    if (MODE == 0) {
        ushort4 hv, lv;
        split1(r.x, hv.x, lv.x); split1(r.y, hv.y, lv.y);
        split1(r.z, hv.z, lv.z); split1(r.w, hv.w, lv.w);
        ((ushort4*)g_m1h)[(size_t)warp * 32 + lane] = hv;
        ((ushort4*)g_m1l)[(size_t)warp * 32 + lane] = lv;
    } else {
        float4 qv = __ldg((const float4*)((const float*)g_q + (size_t)warp * 128) + lane);
        r.x += qv.x; r.y += qv.y; r.z += qv.z; r.w += qv.w;
        ((float4*)(outp + (size_t)warp * 128))[lane] = r;
    }
}

// ---------------- bf16 2-limb tensor-core GEMM (ldmatrix + cp.async pipeline) --
__device__ __forceinline__ void mma_bf16(float c[4], const unsigned a[4], const unsigned b[2]) {
    asm volatile(
        "mma.sync.aligned.m16n8k16.row.col.f32.bf16.bf16.f32 "
        "{%0,%1,%2,%3},{%4,%5,%6,%7},{%8,%9},{%0,%1,%2,%3};"
        : "+f"(c[0]), "+f"(c[1]), "+f"(c[2]), "+f"(c[3])
        : "r"(a[0]), "r"(a[1]), "r"(a[2]), "r"(a[3]), "r"(b[0]), "r"(b[1]));
}

__device__ __forceinline__ void ldsm_x4(unsigned r[4], unsigned addr) {
    asm volatile("ldmatrix.sync.aligned.m8n8.x4.shared.b16 {%0,%1,%2,%3}, [%4];"
        : "=r"(r[0]), "=r"(r[1]), "=r"(r[2]), "=r"(r[3]) : "r"(addr));
}

__device__ __forceinline__ void cpa16(unsigned smem, const void* g) {
    asm volatile("cp.async.cg.shared.global [%0], [%1], 16;" :: "r"(smem), "l"(g));
}

#define S_LD   40                   // halves per row: 80B rows, 16B-aligned, conflict-free
#define PLANE  (128 * S_LD)         // halves per (stage, plane)
#define GSMEM  (8 * PLANE * 2)      // bytes: 4 planes x 2 stages = 80KB

// MODE 0 (layer 1): grid (391,2): h-cols [by*128,+128) = relu(m1@W1l^T + x@W1r^T + b1)
// MODE 1 (layer 2): grid (391,2): by==0: g_pf16 = h@W2l^T ; by==1: g_q = h@W2r^T + b2
template <int K, int MODE>
__global__ void __launch_bounds__(256)
gemm_bf16(const float* __restrict__ biasp) {
    extern __shared__ unsigned short sm[];
    unsigned short* Ah = sm;
    unsigned short* Al = Ah + 2 * PLANE;
    unsigned short* Bh = Al + 2 * PLANE;
    unsigned short* Bl = Bh + 2 * PLANE;

    const int t    = threadIdx.x;
    const int wid  = t >> 5;
    const int lane = t & 31;
    const int g    = lane >> 2;
    const int tig  = lane & 3;
    const int wm   = wid & 3;
    const int wn   = wid >> 2;
    const int row0 = blockIdx.x * 128;
    const int by   = blockIdx.y;

    const int a_row = (lane & 7) + ((lane >> 3) & 1) * 8;
    const int a_col = (lane >> 4) * 8;
    const unsigned uAh = (unsigned)__cvta_generic_to_shared(Ah);
    const unsigned uAl = (unsigned)__cvta_generic_to_shared(Al);
    const unsigned uBh = (unsigned)__cvta_generic_to_shared(Bh);
    const unsigned uBl = (unsigned)__cvta_generic_to_shared(Bl);

    float acc[2][8][4];
    #pragma unroll
    for (int im = 0; im < 2; im++)
        #pragma unroll
        for (int in_ = 0; in_ < 8; in_++)
            #pragma unroll
            for (int c = 0; c < 4; c++) acc[im][in_][c] = 0.f;

    const int TC = 8;

    auto copy_chunk = [&](int c, int st) {
        const unsigned short *Aph, *Apl, *Wph, *Wpl;
        int wrow0, kk;
        if (MODE == 0) {
            int pass = c >> 2; kk = (c & 3) * 32;
            Aph = pass ? g_xh : g_m1h;   Apl = pass ? g_xl : g_m1l;
            Wph = pass ? g_w1rh : g_w1lh; Wpl = pass ? g_w1rl : g_w1ll;
            wrow0 = by * 128;
        } else {
            kk = c * 32;
            Aph = g_hh; Apl = g_hl;
            Wph = (by == 0) ? g_w2lh : g_w2rh;
            Wpl = (by == 0) ? g_w2ll : g_w2rl;
            wrow0 = 0;
        }
        #pragma unroll
        for (int u = 0; u < 2; u++) {
            int idx = t + u * 256;
            int row = idx >> 2;
            int c16 = idx & 3;
            int r  = min(row0 + row, NN - 1);
            int wr = wrow0 + row;
            unsigned so = (unsigned)(st * PLANE + row * S_LD) * 2u + (unsigned)c16 * 16u;
            cpa16(uAh + so, Aph + (size_t)r * K + kk + c16 * 8);
            cpa16(uAl + so, Apl + (size_t)r * K + kk + c16 * 8);
            cpa16(uBh + so, Wph + (size_t)wr * K + kk + c16 * 8);
            cpa16(uBl + so, Wpl + (size_t)wr * K + kk + c16 * 8);
        }
        asm volatile("cp.async.commit_group;" ::: "memory");
    };

    auto compute = [&](int st) {
        const unsigned stoff = (unsigned)(st * PLANE) * 2u;
        #pragma unroll
        for (int o = 0; o < 32; o += 16) {
            unsigned ah[2][4], al[2][4], bh[8][2], bl[8][2];
            #pragma unroll
            for (int im = 0; im < 2; im++) {
                unsigned aoff = ((wm * 32 + im * 16 + a_row) * S_LD + o + a_col) * 2u + stoff;
                ldsm_x4(ah[im], uAh + aoff);
                ldsm_x4(al[im], uAl + aoff);
            }
            #pragma unroll
            for (int q = 0; q < 2; q++) {
                #pragma unroll
                for (int kh = 0; kh < 2; kh++) {
                    unsigned boff = ((wn * 64 + q * 32 + lane) * S_LD + o + kh * 8) * 2u + stoff;
                    unsigned r4[4];
                    ldsm_x4(r4, uBh + boff);
                    #pragma unroll
                    for (int j = 0; j < 4; j++) bh[q * 4 + j][kh] = r4[j];
                    ldsm_x4(r4, uBl + boff);
                    #pragma unroll
                    for (int j = 0; j < 4; j++) bl[q * 4 + j][kh] = r4[j];
                }
            }
            #pragma unroll
            for (int im = 0; im < 2; im++)
                #pragma unroll
                for (int in_ = 0; in_ < 8; in_++) {
                    mma_bf16(acc[im][in_], ah[im], bl[in_]);
                    mma_bf16(acc[im][in_], al[im], bh[in_]);
                    mma_bf16(acc[im][in_], ah[im], bh[in_]);
                }
        }
    };

    copy_chunk(0, 0);
    for (int c = 0; c < TC; c++) {
        if (c + 1 < TC) {
            copy_chunk(c + 1, (c + 1) & 1);
            asm volatile("cp.async.wait_group 1;" ::: "memory");
        } else {
            asm volatile("cp.async.wait_group 0;" ::: "memory");
        }
        __syncthreads();
        compute(c & 1);
        __syncthreads();
    }

    // epilogue
    const float* bias = (MODE == 0) ? biasp : ((by == 1) ? biasp : nullptr);
    const int outcol0 = (MODE == 0) ? by * 128 : 0;
    #pragma unroll
    for (int im = 0; im < 2; im++) {
        #pragma unroll
        for (int in_ = 0; in_ < 8; in_++) {
            int col  = wn * 64 + in_ * 8 + 2 * tig;
            int gcol = outcol0 + col;
            float bx = 0.f, byv = 0.f;
            if (bias) { bx = __ldg(bias + gcol); byv = __ldg(bias + gcol + 1); }
            int r0 = row0 + wm * 32 + im * 16 + g;
            #pragma unroll
            for (int half = 0; half < 2; half++) {
                int r = r0 + half * 8;
                if (r >= NN) continue;
                float vx = acc[im][in_][2 * half + 0] + bx;
                float vy = acc[im][in_][2 * half + 1] + byv;
                if (MODE == 0) {
                    vx = fmaxf(vx, 0.f); vy = fmaxf(vy, 0.f);
                    unsigned short hx, lx, hy, ly;
                    split1(vx, hx, lx); split1(vy, hy, ly);
                    *(unsigned*)&g_hh[(size_t)r * HIDC + gcol] = (unsigned)hx | ((unsigned)hy << 16);
                    *(unsigned*)&g_hl[(size_t)r * HIDC + gcol] = (unsigned)lx | ((unsigned)ly << 16);
                } else if (by == 0) {
                    __half2 hv = __floats2half2_rn(vx, vy);
                    *(unsigned*)&g_pf16[(size_t)r * OUTC + col] = *(unsigned*)&hv;
                } else {
                    *(float2*)(g_q + (size_t)r * OUTC + col) = make_float2(vx, vy);
                }
            }
        }
    }
}

// ---------------- launch ----------------
extern "C" void kernel_launch(void* const* d_in, const int* in_sizes, int n_in,
                              void* d_out, int out_size) {
    const float* x   = (const float*)d_in[0];
    const void*  ei  = d_in[1];
    const float* W1l = (const float*)d_in[2];
    const float* b1  = (const float*)d_in[3];
    const float* W1r = (const float*)d_in[4];
    const float* W2l = (const float*)d_in[5];
    const float* b2  = (const float*)d_in[6];
    const float* W2r = (const float*)d_in[7];
    float* out = (float*)d_out;

    cudaFuncSetAttribute(gemm_bf16<INC, 0>,
                         cudaFuncAttributeMaxDynamicSharedMemorySize, GSMEM);
    cudaFuncSetAttribute(gemm_bf16<HIDC, 1>,
                         cudaFuncAttributeMaxDynamicSharedMemorySize, GSMEM);

    const int NB = (NN + 255) / 256;  // 196

    // prep (splits + deg zero + dtype) || then CSR chain
    prep_kernel<<<SWBLK + SXBLK + NB, 256>>>(ei, x, W1l, W1r, W2l, W2r);
    hist_kernel<<<(EE + 255) / 256, 256>>>(ei);
    scan_partial_kernel<<<NB, 256>>>();
    scan_bsum_kernel<<<1, 256>>>();
    scan_write_kernel<<<NB, 256>>>();
    fill_kernel<<<(EE + 255) / 256, 256>>>(ei);

    // layer 1: m1 = agg(x_f16);  h = relu(m1@W1l^T + x@W1r^T + b1)
    agg128_kernel<0><<<(NN + 7) / 8, 256>>>(nullptr);
    gemm_bf16<INC, 0><<<dim3((NN + 127) / 128, 2), 256, GSMEM>>>(b1);

    // layer 2: p16 = h@W2l^T; q = h@W2r^T + b2;  out = agg(p16) + q
    gemm_bf16<HIDC, 1><<<dim3((NN + 127) / 128, 2), 256, GSMEM>>>(b2);
    agg128_kernel<1><<<(NN + 7) / 8, 256>>>(out);
}